// round 5
// baseline (speedup 1.0000x reference)
#include <cuda_runtime.h>
#include <cuda_bf16.h>
#include <math.h>
#include <stdint.h>

#define BATCH   2
#define SEQ     1024
#define DMODEL  1024
#define NLAYER  4
#define VOCAB   32000
#define DSTATE  16
#define DCONV   4
#define DINNER  2048
#define DTRANK  64
#define TTOK    (BATCH*SEQ)
#define XDBL_W  96

typedef __nv_bfloat16 bf16;

// -------- fp32 scratch --------
__device__ float g_h   [TTOK*DMODEL];
__device__ float g_xz  [TTOK*2*DINNER];
__device__ float g_xc  [TTOK*DINNER];
__device__ float g_xdbl[TTOK*XDBL_W];
__device__ float g_dt  [TTOK*DINNER];
// -------- bf16 hi/lo activations --------
__device__ bf16 g_xn_h[TTOK*DMODEL],  g_xn_l[TTOK*DMODEL];
__device__ bf16 g_xc_h[TTOK*DINNER],  g_xc_l[TTOK*DINNER];
__device__ bf16 g_xd_h[TTOK*XDBL_W],  g_xd_l[TTOK*XDBL_W];
__device__ bf16 g_y_h [TTOK*DINNER],  g_y_l [TTOK*DINNER];
// -------- bf16 hi/lo weights --------
__device__ bf16 g_win_h [NLAYER*2*DINNER*DMODEL], g_win_l [NLAYER*2*DINNER*DMODEL];
__device__ bf16 g_wout_h[NLAYER*DMODEL*DINNER],   g_wout_l[NLAYER*DMODEL*DINNER];
__device__ bf16 g_wxp_h [NLAYER*XDBL_W*DINNER],   g_wxp_l [NLAYER*XDBL_W*DINNER];
__device__ bf16 g_wdt_h [NLAYER*DINNER*DTRANK],   g_wdt_l [NLAYER*DINNER*DTRANK];
__device__ bf16 g_wemb_h[VOCAB*DMODEL],           g_wemb_l[VOCAB*DMODEL];

// ---------------- helpers ----------------
__device__ __forceinline__ void split2(float x, bf16& h, bf16& l) {
    h = __float2bfloat16_rn(x);
    l = __float2bfloat16_rn(x - __bfloat162float(h));
}
__device__ __forceinline__ void cp16(uint32_t dst, const void* src, int srcBytes) {
    asm volatile("cp.async.cg.shared.global [%0], [%1], 16, %2;"
                 :: "r"(dst), "l"(src), "r"(srcBytes));
}
__device__ __forceinline__ void cp_commit() { asm volatile("cp.async.commit_group;"); }
template<int N> __device__ __forceinline__ void cp_wait() {
    asm volatile("cp.async.wait_group %0;" :: "n"(N));
}
__device__ __forceinline__ void ldsm4(uint32_t* r, uint32_t addr) {
    asm volatile("ldmatrix.sync.aligned.m8n8.x4.shared.b16 {%0,%1,%2,%3}, [%4];"
                 : "=r"(r[0]), "=r"(r[1]), "=r"(r[2]), "=r"(r[3]) : "r"(addr));
}
__device__ __forceinline__ void mma16(float* d, const uint32_t* a, uint32_t b0, uint32_t b1) {
    asm volatile(
        "mma.sync.aligned.m16n8k16.row.col.f32.bf16.bf16.f32 "
        "{%0,%1,%2,%3}, {%4,%5,%6,%7}, {%8,%9}, {%0,%1,%2,%3};\n"
        : "+f"(d[0]), "+f"(d[1]), "+f"(d[2]), "+f"(d[3])
        : "r"(a[0]), "r"(a[1]), "r"(a[2]), "r"(a[3]), "r"(b0), "r"(b1));
}

// ---------------- elementwise kernels ----------------
__global__ void embed_k(const int* __restrict__ tok, const float* __restrict__ emb,
                        float* __restrict__ out)
{
    int t = blockIdx.x;
    int row = tok[t];
    ((float4*)(out + (size_t)t * DMODEL))[threadIdx.x] =
        ((const float4*)(emb + (size_t)row * DMODEL))[threadIdx.x];
}

__global__ void split_k(const float* __restrict__ s, bf16* __restrict__ dh,
                        bf16* __restrict__ dl, int n4)
{
    int i = blockIdx.x * blockDim.x + threadIdx.x;
    if (i >= n4) return;
    float4 v = ((const float4*)s)[i];
    bf16 h0,h1,h2,h3,l0,l1,l2,l3;
    split2(v.x,h0,l0); split2(v.y,h1,l1); split2(v.z,h2,l2); split2(v.w,h3,l3);
    uint2 ph, pl;
    ph.x = ((uint32_t)__bfloat16_as_ushort(h1)<<16) | __bfloat16_as_ushort(h0);
    ph.y = ((uint32_t)__bfloat16_as_ushort(h3)<<16) | __bfloat16_as_ushort(h2);
    pl.x = ((uint32_t)__bfloat16_as_ushort(l1)<<16) | __bfloat16_as_ushort(l0);
    pl.y = ((uint32_t)__bfloat16_as_ushort(l3)<<16) | __bfloat16_as_ushort(l2);
    ((uint2*)dh)[i] = ph;
    ((uint2*)dl)[i] = pl;
}

__global__ void rmsnorm_k(const float* __restrict__ x, const float* __restrict__ w,
                          bf16* __restrict__ oh, bf16* __restrict__ ol)
{
    int t = blockIdx.x;
    int tid = threadIdx.x;
    float4 v = ((const float4*)(x + (size_t)t * DMODEL))[tid];
    float ss = v.x*v.x + v.y*v.y + v.z*v.z + v.w*v.w;
    __shared__ float sbuf[8];
    #pragma unroll
    for (int o = 16; o; o >>= 1) ss += __shfl_xor_sync(0xffffffffu, ss, o);
    int warp = tid >> 5, lane = tid & 31;
    if (lane == 0) sbuf[warp] = ss;
    __syncthreads();
    if (warp == 0) {
        float s2 = (lane < 8) ? sbuf[lane] : 0.f;
        #pragma unroll
        for (int o = 4; o; o >>= 1) s2 += __shfl_xor_sync(0xffffffffu, s2, o);
        if (lane == 0) sbuf[0] = rsqrtf(s2 * (1.0f / DMODEL) + 1e-5f);
    }
    __syncthreads();
    float r = sbuf[0];
    float4 wv = ((const float4*)w)[tid];
    float o0 = v.x*r*wv.x, o1 = v.y*r*wv.y, o2 = v.z*r*wv.z, o3 = v.w*r*wv.w;
    bf16 h0,h1,h2,h3,l0,l1,l2,l3;
    split2(o0,h0,l0); split2(o1,h1,l1); split2(o2,h2,l2); split2(o3,h3,l3);
    uint2 ph, pl;
    ph.x = ((uint32_t)__bfloat16_as_ushort(h1)<<16) | __bfloat16_as_ushort(h0);
    ph.y = ((uint32_t)__bfloat16_as_ushort(h3)<<16) | __bfloat16_as_ushort(h2);
    pl.x = ((uint32_t)__bfloat16_as_ushort(l1)<<16) | __bfloat16_as_ushort(l0);
    pl.y = ((uint32_t)__bfloat16_as_ushort(l3)<<16) | __bfloat16_as_ushort(l2);
    ((uint2*)(oh + (size_t)t * DMODEL))[tid] = ph;
    ((uint2*)(ol + (size_t)t * DMODEL))[tid] = pl;
}

__global__ void conv_silu_k(const float* __restrict__ xz, const float* __restrict__ cw,
                            const float* __restrict__ cb, float* __restrict__ xc,
                            bf16* __restrict__ xch, bf16* __restrict__ xcl)
{
    int idx = blockIdx.x * blockDim.x + threadIdx.x;
    if (idx >= TTOK * DINNER) return;
    int c = idx % DINNER;
    int t = idx / DINNER;
    int l = t % SEQ;
    float4 w4 = *(const float4*)(cw + c * 4);
    const size_t str = 2 * DINNER;
    float acc = cb[c];
    if (l >= 3) acc += w4.x * xz[(size_t)(t-3)*str + c];
    if (l >= 2) acc += w4.y * xz[(size_t)(t-2)*str + c];
    if (l >= 1) acc += w4.z * xz[(size_t)(t-1)*str + c];
    acc += w4.w * xz[(size_t)t*str + c];
    float s = 1.f / (1.f + expf(-acc));
    float o = acc * s;
    xc[idx] = o;
    bf16 h, lo; split2(o, h, lo);
    xch[idx] = h; xcl[idx] = lo;
}

__global__ __launch_bounds__(256)
void scan_k(const float* __restrict__ xdbl, const float* __restrict__ dt,
            const float* __restrict__ xc,   const float* __restrict__ xz,
            const float* __restrict__ A_log, const float* __restrict__ Dsk,
            bf16* __restrict__ yh, bf16* __restrict__ yl)
{
    int s = threadIdx.x & 15;
    int c = ((blockIdx.x & 127) << 4) + (threadIdx.x >> 4);
    int b = blockIdx.x >> 7;
    float A = -expf(A_log[(size_t)c * DSTATE + s]);
    float dval = Dsk[c];
    bool lane0 = (s == 0);
    float h = 0.f;
    int tbase = b * SEQ;
    for (int l = 0; l < SEQ; l++) {
        int t = tbase + l;
        float dtv = dt[(size_t)t * DINNER + c];
        float xv  = xc[(size_t)t * DINNER + c];
        float Bv  = xdbl[(size_t)t * XDBL_W + DTRANK + s];
        float Cv  = xdbl[(size_t)t * XDBL_W + DTRANK + DSTATE + s];
        float dA = __expf(dtv * A);
        h = dA * h + (dtv * xv) * Bv;
        float p = h * Cv;
        p += __shfl_xor_sync(0xffffffffu, p, 8);
        p += __shfl_xor_sync(0xffffffffu, p, 4);
        p += __shfl_xor_sync(0xffffffffu, p, 2);
        p += __shfl_xor_sync(0xffffffffu, p, 1);
        if (lane0) {
            float z = xz[(size_t)t * (2*DINNER) + DINNER + c];
            float sg = 1.f / (1.f + __expf(-z));
            float o = (p + dval * xv) * (z * sg);
            bf16 hh, ll; split2(o, hh, ll);
            yh[(size_t)t * DINNER + c] = hh;
            yl[(size_t)t * DINNER + c] = ll;
        }
    }
}

// ----------------------------------------------------------
// Split-bf16 HMMA GEMM (NT): C[2048,N] = A[2048,K] x W[N,K]^T
// acc = Ah*Bh + Ah*Bl + Al*Bh (fp32 accum), mma.m16n8k16.bf16.
// CTA 128x128, 8 warps (2Mx4N), warp tile 64x32, KCH=32 bf16/chunk.
// Smem rows 80B (64B data + 16B pad) -> conflict-free ldmatrix.
// 4-stage cp.async. EPI: 0=store 1=accum 2=softplus+bias 3=store+split
// ----------------------------------------------------------
#define KCH     32
#define ROWB    80
#define TILEB   (128*ROWB)      // 10240 B per tile
#define STAGEB  (4*TILEB)       // Ah|Al|Bh|Bl = 40960 B
#define GSMEM   (4*STAGEB)      // 163840 B

template<int EPI>
__global__ __launch_bounds__(256, 1)
void mma_gemm(const bf16* __restrict__ Ah, const bf16* __restrict__ Al, int lda,
              const bf16* __restrict__ Wh, const bf16* __restrict__ Wl, int ldw,
              float* __restrict__ C, int ldc,
              const float* __restrict__ bias,
              bf16* __restrict__ auxh, bf16* __restrict__ auxl,
              int N, int K)
{
    extern __shared__ char smem[];
    uint32_t sb = (uint32_t)__cvta_generic_to_shared(smem);

    int tid = threadIdx.x, lane = tid & 31, warp = tid >> 5;
    int wm = warp & 1;            // 64-row half
    int wn = warp >> 1;           // 32-col quarter
    int tileM = blockIdx.y * 128, tileN = blockIdx.x * 128;

    float acc[4][4][4];
    #pragma unroll
    for (int mi = 0; mi < 4; mi++)
        #pragma unroll
        for (int ni = 0; ni < 4; ni++)
            #pragma unroll
            for (int e = 0; e < 4; e++) acc[mi][ni][e] = 0.f;

    const int iters = K / KCH;

    // per-lane ldmatrix offsets (within tile)
    uint32_t laneAoff = (uint32_t)((wm*64 + (lane & 15)) * ROWB + ((lane >> 4) & 1) * 16);
    uint32_t laneBoff = (uint32_t)((wn*32 + (lane & 7) + ((lane >= 16) ? 8 : 0)) * ROWB
                                   + ((lane >> 3) & 1) * 16);

    auto load_chunk = [&](int s, int it) {
        int k0 = it * KCH;
        uint32_t sbase = sb + (uint32_t)(s * STAGEB);
        #pragma unroll
        for (int i = 0; i < 8; i++) {
            int task = tid + i * 256;          // 0..2047
            int tile = task >> 9;              // 0=Ah 1=Al 2=Bh 3=Bl
            int r    = (task >> 2) & 127;
            int c16  = task & 3;
            uint32_t dst = sbase + (uint32_t)(tile * TILEB + r * ROWB + c16 * 16);
            size_t eo = (size_t)k0 + c16 * 8;
            if (tile == 0)      cp16(dst, Ah + (size_t)(tileM + r) * lda + eo, 16);
            else if (tile == 1) cp16(dst, Al + (size_t)(tileM + r) * lda + eo, 16);
            else {
                int wr = tileN + r;
                const bf16* base = (tile == 2) ? Wh : Wl;
                const bf16* src = base + (size_t)(wr < N ? wr : 0) * ldw + eo;
                cp16(dst, src, wr < N ? 16 : 0);
            }
        }
        cp_commit();
    };

    int npro = iters < 3 ? iters : 3;
    for (int c = 0; c < npro; c++) load_chunk(c, c);

    for (int it = 0; it < iters; it++) {
        int s = it & 3;
        int rem = iters - 1 - it;
        if (rem >= 2)      cp_wait<2>();
        else if (rem == 1) cp_wait<1>();
        else               cp_wait<0>();
        __syncthreads();

        uint32_t stA_h = sb + s*STAGEB + laneAoff;
        uint32_t stA_l = stA_h + TILEB;
        uint32_t stB_h = sb + s*STAGEB + 2*TILEB + laneBoff;
        uint32_t stB_l = stB_h + TILEB;

        #pragma unroll
        for (int ks = 0; ks < 2; ks++) {
            uint32_t ah[4][4], al[4][4], bh[2][4], bl[2][4];
            #pragma unroll
            for (int mi = 0; mi < 4; mi++) {
                ldsm4(ah[mi], stA_h + mi*16*ROWB + ks*32);
                ldsm4(al[mi], stA_l + mi*16*ROWB + ks*32);
            }
            #pragma unroll
            for (int pi = 0; pi < 2; pi++) {
                ldsm4(bh[pi], stB_h + pi*16*ROWB + ks*32);
                ldsm4(bl[pi], stB_l + pi*16*ROWB + ks*32);
            }
            #pragma unroll
            for (int mi = 0; mi < 4; mi++)
                #pragma unroll
                for (int ni = 0; ni < 4; ni++) {
                    int pi = ni >> 1, j = (ni & 1) * 2;
                    mma16(acc[mi][ni], ah[mi], bh[pi][j], bh[pi][j+1]);
                    mma16(acc[mi][ni], ah[mi], bl[pi][j], bl[pi][j+1]);
                    mma16(acc[mi][ni], al[mi], bh[pi][j], bh[pi][j+1]);
                }
        }
        if (it + 3 < iters) load_chunk((it + 3) & 3, it + 3);
    }

    // ---- epilogue ----
    int g = lane >> 2, t4 = lane & 3;
    int warpN0 = tileN + wn*32;
    #pragma unroll
    for (int mi = 0; mi < 4; mi++) {
        int r0 = tileM + wm*64 + mi*16 + g;
        #pragma unroll
        for (int ni = 0; ni < 4; ni++) {
            int c = warpN0 + ni*8 + 2*t4;
            if (c >= N) continue;
            float2 v0 = make_float2(acc[mi][ni][0], acc[mi][ni][1]);
            float2 v1 = make_float2(acc[mi][ni][2], acc[mi][ni][3]);
            float* p0 = C + (size_t)r0 * ldc + c;
            float* p1 = C + (size_t)(r0 + 8) * ldc + c;
            if (EPI == 1) {
                float2 o0 = *(float2*)p0, o1 = *(float2*)p1;
                v0.x += o0.x; v0.y += o0.y; v1.x += o1.x; v1.y += o1.y;
            } else if (EPI == 2) {
                float b0 = bias[c], b1 = bias[c+1];
                v0.x += b0; v0.y += b1; v1.x += b0; v1.y += b1;
                v0.x = (v0.x > 20.f) ? v0.x : log1pf(expf(v0.x));
                v0.y = (v0.y > 20.f) ? v0.y : log1pf(expf(v0.y));
                v1.x = (v1.x > 20.f) ? v1.x : log1pf(expf(v1.x));
                v1.y = (v1.y > 20.f) ? v1.y : log1pf(expf(v1.y));
            }
            *(float2*)p0 = v0;
            *(float2*)p1 = v1;
            if (EPI == 3) {
                bf16 h0,h1,l0,l1;
                split2(v0.x,h0,l0); split2(v0.y,h1,l1);
                auxh[(size_t)r0*ldc + c] = h0; auxh[(size_t)r0*ldc + c+1] = h1;
                auxl[(size_t)r0*ldc + c] = l0; auxl[(size_t)r0*ldc + c+1] = l1;
                split2(v1.x,h0,l0); split2(v1.y,h1,l1);
                auxh[(size_t)(r0+8)*ldc + c] = h0; auxh[(size_t)(r0+8)*ldc + c+1] = h1;
                auxl[(size_t)(r0+8)*ldc + c] = l0; auxl[(size_t)(r0+8)*ldc + c+1] = l1;
            }
        }
    }
}

// ----------------------------------------------------------
extern "C" void kernel_launch(void* const* d_in, const int* in_sizes, int n_in,
                              void* d_out, int out_size)
{
    const int*   tokens       = (const int*)  d_in[0];
    const float* embed        = (const float*)d_in[1];
    const float* norm_w       = (const float*)d_in[2];
    const float* in_proj_w    = (const float*)d_in[3];
    const float* conv_w       = (const float*)d_in[4];
    const float* conv_b       = (const float*)d_in[5];
    const float* x_proj_w     = (const float*)d_in[6];
    const float* dt_w         = (const float*)d_in[7];
    const float* dt_b         = (const float*)d_in[8];
    const float* A_log        = (const float*)d_in[9];
    const float* D_skip       = (const float*)d_in[10];
    const float* out_proj_w   = (const float*)d_in[11];
    const float* final_norm_w = (const float*)d_in[12];
    float* out = (float*)d_out;

    float *h, *xz, *xc, *xdbl, *dts;
    bf16 *xnh,*xnl,*xch,*xcl,*xdh,*xdl,*yh,*yl;
    bf16 *winh,*winl,*wouth,*woutl,*wxph,*wxpl,*wdth,*wdtl,*wembh,*wembl;
    cudaGetSymbolAddress((void**)&h,    g_h);
    cudaGetSymbolAddress((void**)&xz,   g_xz);
    cudaGetSymbolAddress((void**)&xc,   g_xc);
    cudaGetSymbolAddress((void**)&xdbl, g_xdbl);
    cudaGetSymbolAddress((void**)&dts,  g_dt);
    cudaGetSymbolAddress((void**)&xnh,  g_xn_h);  cudaGetSymbolAddress((void**)&xnl, g_xn_l);
    cudaGetSymbolAddress((void**)&xch,  g_xc_h);  cudaGetSymbolAddress((void**)&xcl, g_xc_l);
    cudaGetSymbolAddress((void**)&xdh,  g_xd_h);  cudaGetSymbolAddress((void**)&xdl, g_xd_l);
    cudaGetSymbolAddress((void**)&yh,   g_y_h);   cudaGetSymbolAddress((void**)&yl,  g_y_l);
    cudaGetSymbolAddress((void**)&winh, g_win_h); cudaGetSymbolAddress((void**)&winl, g_win_l);
    cudaGetSymbolAddress((void**)&wouth,g_wout_h);cudaGetSymbolAddress((void**)&woutl,g_wout_l);
    cudaGetSymbolAddress((void**)&wxph, g_wxp_h); cudaGetSymbolAddress((void**)&wxpl, g_wxp_l);
    cudaGetSymbolAddress((void**)&wdth, g_wdt_h); cudaGetSymbolAddress((void**)&wdtl, g_wdt_l);
    cudaGetSymbolAddress((void**)&wembh,g_wemb_h);cudaGetSymbolAddress((void**)&wembl,g_wemb_l);

    cudaFuncSetAttribute(mma_gemm<0>, cudaFuncAttributeMaxDynamicSharedMemorySize, GSMEM);
    cudaFuncSetAttribute(mma_gemm<1>, cudaFuncAttributeMaxDynamicSharedMemorySize, GSMEM);
    cudaFuncSetAttribute(mma_gemm<2>, cudaFuncAttributeMaxDynamicSharedMemorySize, GSMEM);
    cudaFuncSetAttribute(mma_gemm<3>, cudaFuncAttributeMaxDynamicSharedMemorySize, GSMEM);

    // one-pass hi/lo split of all weights
    {
        int n4;
        n4 = NLAYER*2*DINNER*DMODEL/4; split_k<<<(n4+255)/256, 256>>>(in_proj_w,  winh,  winl,  n4);
        n4 = NLAYER*DMODEL*DINNER/4;   split_k<<<(n4+255)/256, 256>>>(out_proj_w, wouth, woutl, n4);
        n4 = NLAYER*XDBL_W*DINNER/4;   split_k<<<(n4+255)/256, 256>>>(x_proj_w,   wxph,  wxpl,  n4);
        n4 = NLAYER*DINNER*DTRANK/4;   split_k<<<(n4+255)/256, 256>>>(dt_w,       wdth,  wdtl,  n4);
        n4 = VOCAB*DMODEL/4;           split_k<<<(n4+255)/256, 256>>>(embed,      wembh, wembl, n4);
    }

    embed_k<<<TTOK, 256>>>(tokens, embed, h);

    for (int L = 0; L < NLAYER; L++) {
        rmsnorm_k<<<TTOK, 256>>>(h, norm_w + (size_t)L * DMODEL, xnh, xnl);

        // in_proj: [2048,1024] x [4096,1024]^T -> xz (fp32)
        mma_gemm<0><<<dim3(2*DINNER/128, TTOK/128), 256, GSMEM>>>(
            xnh, xnl, DMODEL,
            winh + (size_t)L * 2*DINNER*DMODEL, winl + (size_t)L * 2*DINNER*DMODEL, DMODEL,
            xz, 2*DINNER, nullptr, nullptr, nullptr, 2*DINNER, DMODEL);

        conv_silu_k<<<(TTOK*DINNER + 255)/256, 256>>>(
            xz, conv_w + (size_t)L * DINNER*DCONV, conv_b + (size_t)L * DINNER,
            xc, xch, xcl);

        // x_proj: [2048,2048] x [96,2048]^T -> xdbl (fp32 + hi/lo)
        mma_gemm<3><<<dim3(1, TTOK/128), 256, GSMEM>>>(
            xch, xcl, DINNER,
            wxph + (size_t)L * XDBL_W*DINNER, wxpl + (size_t)L * XDBL_W*DINNER, DINNER,
            xdbl, XDBL_W, nullptr, xdh, xdl, XDBL_W, DINNER);

        // dt: softplus([2048,96(:64)] x [2048,64]^T + dt_b)
        mma_gemm<2><<<dim3(DINNER/128, TTOK/128), 256, GSMEM>>>(
            xdh, xdl, XDBL_W,
            wdth + (size_t)L * DINNER*DTRANK, wdtl + (size_t)L * DINNER*DTRANK, DTRANK,
            dts, DINNER, dt_b + (size_t)L * DINNER, nullptr, nullptr, DINNER, DTRANK);

        scan_k<<<256, 256>>>(xdbl, dts, xc, xz,
                             A_log + (size_t)L * DINNER*DSTATE,
                             D_skip + (size_t)L * DINNER, yh, yl);

        // out_proj (+residual): [2048,2048] x [1024,2048]^T += h
        mma_gemm<1><<<dim3(DMODEL/128, TTOK/128), 256, GSMEM>>>(
            yh, yl, DINNER,
            wouth + (size_t)L * DMODEL*DINNER, woutl + (size_t)L * DMODEL*DINNER, DINNER,
            h, DMODEL, nullptr, nullptr, nullptr, DMODEL, DINNER);
    }

    rmsnorm_k<<<TTOK, 256>>>(h, final_norm_w, xnh, xnl);

    // logits: [2048,1024] x [32000,1024]^T
    mma_gemm<0><<<dim3(VOCAB/128, TTOK/128), 256, GSMEM>>>(
        xnh, xnl, DMODEL, wembh, wembl, DMODEL,
        out, VOCAB, nullptr, nullptr, nullptr, VOCAB, DMODEL);
}

// round 6
// speedup vs baseline: 1.3855x; 1.3855x over previous
#include <cuda_runtime.h>
#include <cuda_fp16.h>
#include <math.h>
#include <stdint.h>

#define BATCH   2
#define SEQ     1024
#define DMODEL  1024
#define NLAYER  4
#define VOCAB   32000
#define DSTATE  16
#define DCONV   4
#define DINNER  2048
#define DTRANK  64
#define TTOK    (BATCH*SEQ)
#define XDBL_W  96

// -------- fp32 scratch --------
__device__ float g_h   [TTOK*DMODEL];
__device__ float g_xz  [TTOK*2*DINNER];
__device__ float g_xc  [TTOK*DINNER];
__device__ float g_xdbl[TTOK*XDBL_W];
__device__ float g_dt  [TTOK*DINNER];
// -------- fp16 activations --------
__device__ __half g_xn_f[TTOK*DMODEL];
__device__ __half g_xc_f[TTOK*DINNER];
__device__ __half g_xd_f[TTOK*XDBL_W];
__device__ __half g_y_f [TTOK*DINNER];
// -------- fp16 weights --------
__device__ __half g_win_f [NLAYER*2*DINNER*DMODEL];
__device__ __half g_wout_f[NLAYER*DMODEL*DINNER];
__device__ __half g_wxp_f [NLAYER*XDBL_W*DINNER];
__device__ __half g_wdt_f [NLAYER*DINNER*DTRANK];
__device__ __half g_wemb_f[VOCAB*DMODEL];

// ---------------- helpers ----------------
__device__ __forceinline__ void cp16(uint32_t dst, const void* src, int srcBytes) {
    asm volatile("cp.async.cg.shared.global [%0], [%1], 16, %2;"
                 :: "r"(dst), "l"(src), "r"(srcBytes));
}
__device__ __forceinline__ void cp_commit() { asm volatile("cp.async.commit_group;"); }
template<int N> __device__ __forceinline__ void cp_wait() {
    asm volatile("cp.async.wait_group %0;" :: "n"(N));
}
__device__ __forceinline__ void ldsm4(uint32_t* r, uint32_t addr) {
    asm volatile("ldmatrix.sync.aligned.m8n8.x4.shared.b16 {%0,%1,%2,%3}, [%4];"
                 : "=r"(r[0]), "=r"(r[1]), "=r"(r[2]), "=r"(r[3]) : "r"(addr));
}
__device__ __forceinline__ void mma16(float* d, const uint32_t* a, uint32_t b0, uint32_t b1) {
    asm volatile(
        "mma.sync.aligned.m16n8k16.row.col.f32.f16.f16.f32 "
        "{%0,%1,%2,%3}, {%4,%5,%6,%7}, {%8,%9}, {%0,%1,%2,%3};\n"
        : "+f"(d[0]), "+f"(d[1]), "+f"(d[2]), "+f"(d[3])
        : "r"(a[0]), "r"(a[1]), "r"(a[2]), "r"(a[3]), "r"(b0), "r"(b1));
}
__device__ __forceinline__ uint32_t pack2h(float a, float b) {
    __half2 p = __floats2half2_rn(a, b);
    return *(uint32_t*)&p;
}

// ---------------- elementwise kernels ----------------
__global__ void embed_k(const int* __restrict__ tok, const float* __restrict__ emb,
                        float* __restrict__ out)
{
    int t = blockIdx.x;
    int row = tok[t];
    ((float4*)(out + (size_t)t * DMODEL))[threadIdx.x] =
        ((const float4*)(emb + (size_t)row * DMODEL))[threadIdx.x];
}

__global__ void cvt_h_k(const float* __restrict__ s, __half* __restrict__ d, int n4)
{
    int i = blockIdx.x * blockDim.x + threadIdx.x;
    if (i >= n4) return;
    float4 v = ((const float4*)s)[i];
    uint2 p;
    p.x = pack2h(v.x, v.y);
    p.y = pack2h(v.z, v.w);
    ((uint2*)d)[i] = p;
}

__global__ void rmsnorm_k(const float* __restrict__ x, const float* __restrict__ w,
                          __half* __restrict__ oh)
{
    int t = blockIdx.x;
    int tid = threadIdx.x;
    float4 v = ((const float4*)(x + (size_t)t * DMODEL))[tid];
    float ss = v.x*v.x + v.y*v.y + v.z*v.z + v.w*v.w;
    __shared__ float sbuf[8];
    #pragma unroll
    for (int o = 16; o; o >>= 1) ss += __shfl_xor_sync(0xffffffffu, ss, o);
    int warp = tid >> 5, lane = tid & 31;
    if (lane == 0) sbuf[warp] = ss;
    __syncthreads();
    if (warp == 0) {
        float s2 = (lane < 8) ? sbuf[lane] : 0.f;
        #pragma unroll
        for (int o = 4; o; o >>= 1) s2 += __shfl_xor_sync(0xffffffffu, s2, o);
        if (lane == 0) sbuf[0] = rsqrtf(s2 * (1.0f / DMODEL) + 1e-5f);
    }
    __syncthreads();
    float r = sbuf[0];
    float4 wv = ((const float4*)w)[tid];
    uint2 p;
    p.x = pack2h(v.x*r*wv.x, v.y*r*wv.y);
    p.y = pack2h(v.z*r*wv.z, v.w*r*wv.w);
    ((uint2*)(oh + (size_t)t * DMODEL))[tid] = p;
}

__global__ void conv_silu_k(const float* __restrict__ xz, const float* __restrict__ cw,
                            const float* __restrict__ cb, float* __restrict__ xc,
                            __half* __restrict__ xch)
{
    int idx = blockIdx.x * blockDim.x + threadIdx.x;
    if (idx >= TTOK * DINNER) return;
    int c = idx % DINNER;
    int t = idx / DINNER;
    int l = t % SEQ;
    float4 w4 = *(const float4*)(cw + c * 4);
    const size_t str = 2 * DINNER;
    float acc = cb[c];
    if (l >= 3) acc += w4.x * xz[(size_t)(t-3)*str + c];
    if (l >= 2) acc += w4.y * xz[(size_t)(t-2)*str + c];
    if (l >= 1) acc += w4.z * xz[(size_t)(t-1)*str + c];
    acc += w4.w * xz[(size_t)t*str + c];
    float s = 1.f / (1.f + expf(-acc));
    float o = acc * s;
    xc[idx] = o;
    xch[idx] = __float2half_rn(o);
}

__global__ __launch_bounds__(256)
void scan_k(const float* __restrict__ xdbl, const float* __restrict__ dt,
            const float* __restrict__ xc,   const float* __restrict__ xz,
            const float* __restrict__ A_log, const float* __restrict__ Dsk,
            __half* __restrict__ yh)
{
    int s = threadIdx.x & 15;
    int c = ((blockIdx.x & 127) << 4) + (threadIdx.x >> 4);
    int b = blockIdx.x >> 7;
    float A = -expf(A_log[(size_t)c * DSTATE + s]);
    float dval = Dsk[c];
    bool lane0 = (s == 0);
    float h = 0.f;
    int tbase = b * SEQ;
    for (int l = 0; l < SEQ; l++) {
        int t = tbase + l;
        float dtv = dt[(size_t)t * DINNER + c];
        float xv  = xc[(size_t)t * DINNER + c];
        float Bv  = xdbl[(size_t)t * XDBL_W + DTRANK + s];
        float Cv  = xdbl[(size_t)t * XDBL_W + DTRANK + DSTATE + s];
        float dA = __expf(dtv * A);
        h = dA * h + (dtv * xv) * Bv;
        float p = h * Cv;
        p += __shfl_xor_sync(0xffffffffu, p, 8);
        p += __shfl_xor_sync(0xffffffffu, p, 4);
        p += __shfl_xor_sync(0xffffffffu, p, 2);
        p += __shfl_xor_sync(0xffffffffu, p, 1);
        if (lane0) {
            float z = xz[(size_t)t * (2*DINNER) + DINNER + c];
            float sg = 1.f / (1.f + __expf(-z));
            yh[(size_t)t * DINNER + c] = __float2half_rn((p + dval * xv) * (z * sg));
        }
    }
}

// ----------------------------------------------------------
// FP16 HMMA GEMM (NT): C[2048,N] = A[2048,K] x W[N,K]^T
// Single-term fp16 (11-bit mantissa == tf32 precision), fp32 accum.
// CTA 128x128, 8 warps (2Mx4N), warp tile 64x32, KCH=32 fp16/chunk.
// Smem rows 80B (64B data + 16B pad) -> conflict-free ldmatrix.
// 4-stage cp.async. EPI: 0=store 1=accum 2=softplus+bias 3=store+fp16aux
// ----------------------------------------------------------
#define KCH     32
#define ROWB    80
#define TILEB   (128*ROWB)      // 10240 B
#define STAGEB  (2*TILEB)       // A|B = 20480 B
#define GSMEM   (4*STAGEB)      // 81920 B

template<int EPI>
__global__ __launch_bounds__(256, 1)
void mma_gemm(const __half* __restrict__ A, int lda,
              const __half* __restrict__ W, int ldw,
              float* __restrict__ C, int ldc,
              const float* __restrict__ bias,
              __half* __restrict__ aux,
              int N, int K)
{
    extern __shared__ char smem[];
    uint32_t sb = (uint32_t)__cvta_generic_to_shared(smem);

    int tid = threadIdx.x, lane = tid & 31, warp = tid >> 5;
    int wm = warp & 1;            // 64-row half
    int wn = warp >> 1;           // 32-col quarter
    int tileM = blockIdx.y * 128, tileN = blockIdx.x * 128;

    float acc[4][4][4];
    #pragma unroll
    for (int mi = 0; mi < 4; mi++)
        #pragma unroll
        for (int ni = 0; ni < 4; ni++)
            #pragma unroll
            for (int e = 0; e < 4; e++) acc[mi][ni][e] = 0.f;

    const int iters = K / KCH;

    uint32_t laneAoff = (uint32_t)((wm*64 + (lane & 15)) * ROWB + ((lane >> 4) & 1) * 16);
    uint32_t laneBoff = (uint32_t)((wn*32 + (lane & 7) + ((lane >= 16) ? 8 : 0)) * ROWB
                                   + ((lane >> 3) & 1) * 16);

    auto load_chunk = [&](int s, int it) {
        int k0 = it * KCH;
        uint32_t sbase = sb + (uint32_t)(s * STAGEB);
        #pragma unroll
        for (int i = 0; i < 4; i++) {
            int task = tid + i * 256;          // 0..1023
            int tile = task >> 9;              // 0=A 1=B
            int r    = (task >> 2) & 127;
            int c16  = task & 3;
            uint32_t dst = sbase + (uint32_t)(tile * TILEB + r * ROWB + c16 * 16);
            size_t eo = (size_t)k0 + c16 * 8;
            if (tile == 0) {
                cp16(dst, A + (size_t)(tileM + r) * lda + eo, 16);
            } else {
                int wr = tileN + r;
                const __half* src = W + (size_t)(wr < N ? wr : 0) * ldw + eo;
                cp16(dst, src, wr < N ? 16 : 0);
            }
        }
        cp_commit();
    };

    int npro = iters < 3 ? iters : 3;
    for (int c = 0; c < npro; c++) load_chunk(c, c);

    for (int it = 0; it < iters; it++) {
        int s = it & 3;
        int rem = iters - 1 - it;
        if (rem >= 2)      cp_wait<2>();
        else if (rem == 1) cp_wait<1>();
        else               cp_wait<0>();
        __syncthreads();

        uint32_t stA = sb + s*STAGEB + laneAoff;
        uint32_t stB = sb + s*STAGEB + TILEB + laneBoff;

        #pragma unroll
        for (int ks = 0; ks < 2; ks++) {
            uint32_t a[4][4], b[2][4];
            #pragma unroll
            for (int mi = 0; mi < 4; mi++)
                ldsm4(a[mi], stA + mi*16*ROWB + ks*32);
            #pragma unroll
            for (int pi = 0; pi < 2; pi++)
                ldsm4(b[pi], stB + pi*16*ROWB + ks*32);
            #pragma unroll
            for (int mi = 0; mi < 4; mi++)
                #pragma unroll
                for (int ni = 0; ni < 4; ni++) {
                    int pi = ni >> 1, j = (ni & 1) * 2;
                    mma16(acc[mi][ni], a[mi], b[pi][j], b[pi][j+1]);
                }
        }
        if (it + 3 < iters) load_chunk((it + 3) & 3, it + 3);
    }

    // ---- epilogue ----
    int g = lane >> 2, t4 = lane & 3;
    int warpN0 = tileN + wn*32;
    #pragma unroll
    for (int mi = 0; mi < 4; mi++) {
        int r0 = tileM + wm*64 + mi*16 + g;
        #pragma unroll
        for (int ni = 0; ni < 4; ni++) {
            int c = warpN0 + ni*8 + 2*t4;
            if (c >= N) continue;
            float2 v0 = make_float2(acc[mi][ni][0], acc[mi][ni][1]);
            float2 v1 = make_float2(acc[mi][ni][2], acc[mi][ni][3]);
            float* p0 = C + (size_t)r0 * ldc + c;
            float* p1 = C + (size_t)(r0 + 8) * ldc + c;
            if (EPI == 1) {
                float2 o0 = *(float2*)p0, o1 = *(float2*)p1;
                v0.x += o0.x; v0.y += o0.y; v1.x += o1.x; v1.y += o1.y;
            } else if (EPI == 2) {
                float b0 = bias[c], b1 = bias[c+1];
                v0.x += b0; v0.y += b1; v1.x += b0; v1.y += b1;
                v0.x = (v0.x > 20.f) ? v0.x : log1pf(expf(v0.x));
                v0.y = (v0.y > 20.f) ? v0.y : log1pf(expf(v0.y));
                v1.x = (v1.x > 20.f) ? v1.x : log1pf(expf(v1.x));
                v1.y = (v1.y > 20.f) ? v1.y : log1pf(expf(v1.y));
            }
            *(float2*)p0 = v0;
            *(float2*)p1 = v1;
            if (EPI == 3) {
                *(uint32_t*)(aux + (size_t)r0*ldc + c)     = pack2h(v0.x, v0.y);
                *(uint32_t*)(aux + (size_t)(r0+8)*ldc + c) = pack2h(v1.x, v1.y);
            }
        }
    }
}

// ----------------------------------------------------------
extern "C" void kernel_launch(void* const* d_in, const int* in_sizes, int n_in,
                              void* d_out, int out_size)
{
    const int*   tokens       = (const int*)  d_in[0];
    const float* embed        = (const float*)d_in[1];
    const float* norm_w       = (const float*)d_in[2];
    const float* in_proj_w    = (const float*)d_in[3];
    const float* conv_w       = (const float*)d_in[4];
    const float* conv_b       = (const float*)d_in[5];
    const float* x_proj_w     = (const float*)d_in[6];
    const float* dt_w         = (const float*)d_in[7];
    const float* dt_b         = (const float*)d_in[8];
    const float* A_log        = (const float*)d_in[9];
    const float* D_skip       = (const float*)d_in[10];
    const float* out_proj_w   = (const float*)d_in[11];
    const float* final_norm_w = (const float*)d_in[12];
    float* out = (float*)d_out;

    float *h, *xz, *xc, *xdbl, *dts;
    __half *xnf,*xcf,*xdf,*yf;
    __half *winf,*woutf,*wxpf,*wdtf,*wembf;
    cudaGetSymbolAddress((void**)&h,    g_h);
    cudaGetSymbolAddress((void**)&xz,   g_xz);
    cudaGetSymbolAddress((void**)&xc,   g_xc);
    cudaGetSymbolAddress((void**)&xdbl, g_xdbl);
    cudaGetSymbolAddress((void**)&dts,  g_dt);
    cudaGetSymbolAddress((void**)&xnf,  g_xn_f);
    cudaGetSymbolAddress((void**)&xcf,  g_xc_f);
    cudaGetSymbolAddress((void**)&xdf,  g_xd_f);
    cudaGetSymbolAddress((void**)&yf,   g_y_f);
    cudaGetSymbolAddress((void**)&winf, g_win_f);
    cudaGetSymbolAddress((void**)&woutf,g_wout_f);
    cudaGetSymbolAddress((void**)&wxpf, g_wxp_f);
    cudaGetSymbolAddress((void**)&wdtf, g_wdt_f);
    cudaGetSymbolAddress((void**)&wembf,g_wemb_f);

    cudaFuncSetAttribute(mma_gemm<0>, cudaFuncAttributeMaxDynamicSharedMemorySize, GSMEM);
    cudaFuncSetAttribute(mma_gemm<1>, cudaFuncAttributeMaxDynamicSharedMemorySize, GSMEM);
    cudaFuncSetAttribute(mma_gemm<2>, cudaFuncAttributeMaxDynamicSharedMemorySize, GSMEM);
    cudaFuncSetAttribute(mma_gemm<3>, cudaFuncAttributeMaxDynamicSharedMemorySize, GSMEM);

    // one-pass fp16 conversion of all weights
    {
        int n4;
        n4 = NLAYER*2*DINNER*DMODEL/4; cvt_h_k<<<(n4+255)/256, 256>>>(in_proj_w,  winf,  n4);
        n4 = NLAYER*DMODEL*DINNER/4;   cvt_h_k<<<(n4+255)/256, 256>>>(out_proj_w, woutf, n4);
        n4 = NLAYER*XDBL_W*DINNER/4;   cvt_h_k<<<(n4+255)/256, 256>>>(x_proj_w,   wxpf,  n4);
        n4 = NLAYER*DINNER*DTRANK/4;   cvt_h_k<<<(n4+255)/256, 256>>>(dt_w,       wdtf,  n4);
        n4 = VOCAB*DMODEL/4;           cvt_h_k<<<(n4+255)/256, 256>>>(embed,      wembf, n4);
    }

    embed_k<<<TTOK, 256>>>(tokens, embed, h);

    for (int L = 0; L < NLAYER; L++) {
        rmsnorm_k<<<TTOK, 256>>>(h, norm_w + (size_t)L * DMODEL, xnf);

        // in_proj: [2048,1024] x [4096,1024]^T -> xz (fp32)
        mma_gemm<0><<<dim3(2*DINNER/128, TTOK/128), 256, GSMEM>>>(
            xnf, DMODEL, winf + (size_t)L * 2*DINNER*DMODEL, DMODEL,
            xz, 2*DINNER, nullptr, nullptr, 2*DINNER, DMODEL);

        conv_silu_k<<<(TTOK*DINNER + 255)/256, 256>>>(
            xz, conv_w + (size_t)L * DINNER*DCONV, conv_b + (size_t)L * DINNER,
            xc, xcf);

        // x_proj: [2048,2048] x [96,2048]^T -> xdbl (fp32 + fp16 aux)
        mma_gemm<3><<<dim3(1, TTOK/128), 256, GSMEM>>>(
            xcf, DINNER, wxpf + (size_t)L * XDBL_W*DINNER, DINNER,
            xdbl, XDBL_W, nullptr, xdf, XDBL_W, DINNER);

        // dt: softplus([2048,96(:64)] x [2048,64]^T + dt_b)
        mma_gemm<2><<<dim3(DINNER/128, TTOK/128), 256, GSMEM>>>(
            xdf, XDBL_W, wdtf + (size_t)L * DINNER*DTRANK, DTRANK,
            dts, DINNER, dt_b + (size_t)L * DINNER, nullptr, DINNER, DTRANK);

        scan_k<<<256, 256>>>(xdbl, dts, xc, xz,
                             A_log + (size_t)L * DINNER*DSTATE,
                             D_skip + (size_t)L * DINNER, yf);

        // out_proj (+residual): [2048,2048] x [1024,2048]^T += h
        mma_gemm<1><<<dim3(DMODEL/128, TTOK/128), 256, GSMEM>>>(
            yf, DINNER, woutf + (size_t)L * DMODEL*DINNER, DINNER,
            h, DMODEL, nullptr, nullptr, DMODEL, DINNER);
    }

    rmsnorm_k<<<TTOK, 256>>>(h, final_norm_w, xnf);

    // logits: [2048,1024] x [32000,1024]^T
    mma_gemm<0><<<dim3(VOCAB/128, TTOK/128), 256, GSMEM>>>(
        xnf, DMODEL, wembf, DMODEL, out, VOCAB, nullptr, nullptr, VOCAB, DMODEL);
}

// round 7
// speedup vs baseline: 1.4012x; 1.0113x over previous
#include <cuda_runtime.h>
#include <cuda_fp16.h>
#include <math.h>
#include <stdint.h>

#define BATCH   2
#define SEQ     1024
#define DMODEL  1024
#define NLAYER  4
#define VOCAB   32000
#define DSTATE  16
#define DCONV   4
#define DINNER  2048
#define DTRANK  64
#define TTOK    (BATCH*SEQ)
#define XDBL_W  96

// -------- fp32 scratch --------
__device__ float g_h   [TTOK*DMODEL];
__device__ float g_xz  [TTOK*2*DINNER];
__device__ float g_xc  [TTOK*DINNER];
__device__ float g_xdbl[TTOK*XDBL_W];
__device__ float g_dt  [TTOK*DINNER];
// -------- fp16 activations --------
__device__ __half g_xn_f[TTOK*DMODEL];
__device__ __half g_xc_f[TTOK*DINNER];
__device__ __half g_xd_f[TTOK*XDBL_W];
__device__ __half g_y_f [TTOK*DINNER];
// -------- fp16 weights --------
__device__ __half g_win_f [NLAYER*2*DINNER*DMODEL];
__device__ __half g_wout_f[NLAYER*DMODEL*DINNER];
__device__ __half g_wxp_f [NLAYER*XDBL_W*DINNER];
__device__ __half g_wdt_f [NLAYER*DINNER*DTRANK];
__device__ __half g_wemb_f[VOCAB*DMODEL];

// ---------------- helpers ----------------
__device__ __forceinline__ void cp16(uint32_t dst, const void* src, int srcBytes) {
    asm volatile("cp.async.cg.shared.global [%0], [%1], 16, %2;"
                 :: "r"(dst), "l"(src), "r"(srcBytes));
}
__device__ __forceinline__ void cp_commit() { asm volatile("cp.async.commit_group;"); }
template<int N> __device__ __forceinline__ void cp_wait() {
    asm volatile("cp.async.wait_group %0;" :: "n"(N));
}
__device__ __forceinline__ void ldsm4(uint32_t* r, uint32_t addr) {
    asm volatile("ldmatrix.sync.aligned.m8n8.x4.shared.b16 {%0,%1,%2,%3}, [%4];"
                 : "=r"(r[0]), "=r"(r[1]), "=r"(r[2]), "=r"(r[3]) : "r"(addr));
}
__device__ __forceinline__ void mma16(float* d, const uint32_t* a, uint32_t b0, uint32_t b1) {
    asm volatile(
        "mma.sync.aligned.m16n8k16.row.col.f32.f16.f16.f32 "
        "{%0,%1,%2,%3}, {%4,%5,%6,%7}, {%8,%9}, {%0,%1,%2,%3};\n"
        : "+f"(d[0]), "+f"(d[1]), "+f"(d[2]), "+f"(d[3])
        : "r"(a[0]), "r"(a[1]), "r"(a[2]), "r"(a[3]), "r"(b0), "r"(b1));
}
__device__ __forceinline__ uint32_t pack2h(float a, float b) {
    __half2 p = __floats2half2_rn(a, b);
    return *(uint32_t*)&p;
}

// ---------------- elementwise kernels ----------------
__global__ void embed_k(const int* __restrict__ tok, const float* __restrict__ emb,
                        float* __restrict__ out)
{
    int t = blockIdx.x;
    int row = tok[t];
    ((float4*)(out + (size_t)t * DMODEL))[threadIdx.x] =
        ((const float4*)(emb + (size_t)row * DMODEL))[threadIdx.x];
}

__global__ void cvt_h_k(const float* __restrict__ s, __half* __restrict__ d, int n4)
{
    int i = blockIdx.x * blockDim.x + threadIdx.x;
    if (i >= n4) return;
    float4 v = ((const float4*)s)[i];
    uint2 p;
    p.x = pack2h(v.x, v.y);
    p.y = pack2h(v.z, v.w);
    ((uint2*)d)[i] = p;
}

__global__ void rmsnorm_k(const float* __restrict__ x, const float* __restrict__ w,
                          __half* __restrict__ oh)
{
    int t = blockIdx.x;
    int tid = threadIdx.x;
    float4 v = ((const float4*)(x + (size_t)t * DMODEL))[tid];
    float ss = v.x*v.x + v.y*v.y + v.z*v.z + v.w*v.w;
    __shared__ float sbuf[8];
    #pragma unroll
    for (int o = 16; o; o >>= 1) ss += __shfl_xor_sync(0xffffffffu, ss, o);
    int warp = tid >> 5, lane = tid & 31;
    if (lane == 0) sbuf[warp] = ss;
    __syncthreads();
    if (warp == 0) {
        float s2 = (lane < 8) ? sbuf[lane] : 0.f;
        #pragma unroll
        for (int o = 4; o; o >>= 1) s2 += __shfl_xor_sync(0xffffffffu, s2, o);
        if (lane == 0) sbuf[0] = rsqrtf(s2 * (1.0f / DMODEL) + 1e-5f);
    }
    __syncthreads();
    float r = sbuf[0];
    float4 wv = ((const float4*)w)[tid];
    uint2 p;
    p.x = pack2h(v.x*r*wv.x, v.y*r*wv.y);
    p.y = pack2h(v.z*r*wv.z, v.w*r*wv.w);
    ((uint2*)(oh + (size_t)t * DMODEL))[tid] = p;
}

__global__ void conv_silu_k(const float* __restrict__ xz, const float* __restrict__ cw,
                            const float* __restrict__ cb, float* __restrict__ xc,
                            __half* __restrict__ xch)
{
    int idx = blockIdx.x * blockDim.x + threadIdx.x;
    if (idx >= TTOK * DINNER) return;
    int c = idx % DINNER;
    int t = idx / DINNER;
    int l = t % SEQ;
    float4 w4 = *(const float4*)(cw + c * 4);
    const size_t str = 2 * DINNER;
    float acc = cb[c];
    if (l >= 3) acc += w4.x * xz[(size_t)(t-3)*str + c];
    if (l >= 2) acc += w4.y * xz[(size_t)(t-2)*str + c];
    if (l >= 1) acc += w4.z * xz[(size_t)(t-1)*str + c];
    acc += w4.w * xz[(size_t)t*str + c];
    float s = 1.f / (1.f + expf(-acc));
    float o = acc * s;
    xc[idx] = o;
    xch[idx] = __float2half_rn(o);
}

__global__ __launch_bounds__(256)
void scan_k(const float* __restrict__ xdbl, const float* __restrict__ dt,
            const float* __restrict__ xc,   const float* __restrict__ xz,
            const float* __restrict__ A_log, const float* __restrict__ Dsk,
            __half* __restrict__ yh)
{
    int s = threadIdx.x & 15;
    int c = ((blockIdx.x & 127) << 4) + (threadIdx.x >> 4);
    int b = blockIdx.x >> 7;
    float A = -expf(A_log[(size_t)c * DSTATE + s]);
    float dval = Dsk[c];
    bool lane0 = (s == 0);
    float h = 0.f;
    int tbase = b * SEQ;
    for (int l = 0; l < SEQ; l++) {
        int t = tbase + l;
        float dtv = dt[(size_t)t * DINNER + c];
        float xv  = xc[(size_t)t * DINNER + c];
        float Bv  = xdbl[(size_t)t * XDBL_W + DTRANK + s];
        float Cv  = xdbl[(size_t)t * XDBL_W + DTRANK + DSTATE + s];
        float dA = __expf(dtv * A);
        h = dA * h + (dtv * xv) * Bv;
        float p = h * Cv;
        p += __shfl_xor_sync(0xffffffffu, p, 8);
        p += __shfl_xor_sync(0xffffffffu, p, 4);
        p += __shfl_xor_sync(0xffffffffu, p, 2);
        p += __shfl_xor_sync(0xffffffffu, p, 1);
        if (lane0) {
            float z = xz[(size_t)t * (2*DINNER) + DINNER + c];
            float sg = 1.f / (1.f + __expf(-z));
            yh[(size_t)t * DINNER + c] = __float2half_rn((p + dval * xv) * (z * sg));
        }
    }
}

// ----------------------------------------------------------
// FP16 HMMA GEMM (NT): C[2048,N] = A[2048,K] x W[N,K]^T
// CTA 128xBN, 8 warps (2M x 4N), warp tile 64x(BN/4), KCH=64.
// Rows 144B (128B data + 16B pad) -> conflict-free ldmatrix.
// 3-stage cp.async, prefetch issued after barrier (safe 3-buffer reuse).
// EPI: 0=store 1=accum 2=softplus+bias 3=store+fp16aux
// ----------------------------------------------------------
#define KCH     64
#define ROWB    144
#define TILEA   (128*ROWB)

template<int EPI, int BN>
__global__ __launch_bounds__(256, 1)
void mma_gemm(const __half* __restrict__ A, int lda,
              const __half* __restrict__ W, int ldw,
              float* __restrict__ C, int ldc,
              const float* __restrict__ bias,
              __half* __restrict__ aux,
              int N, int K)
{
    constexpr int WN    = BN / 4;          // warp N tile (32 or 64)
    constexpr int NFR   = WN / 8;          // n8 frags per warp
    constexpr int NBL   = WN / 16;         // B ldsm.x4 per k16-slice
    constexpr int TILEB = BN * ROWB;
    constexpr int STAGE = TILEA + TILEB;
    constexpr int NTASK = (128 + BN) * 8;  // cp16 per chunk

    extern __shared__ char smem[];
    uint32_t sb = (uint32_t)__cvta_generic_to_shared(smem);

    int tid = threadIdx.x, lane = tid & 31, warp = tid >> 5;
    int wm = warp & 1;
    int wn = warp >> 1;
    int tileM = blockIdx.y * 128, tileN = blockIdx.x * BN;

    float acc[4][NFR][4];
    #pragma unroll
    for (int mi = 0; mi < 4; mi++)
        #pragma unroll
        for (int ni = 0; ni < NFR; ni++)
            #pragma unroll
            for (int e = 0; e < 4; e++) acc[mi][ni][e] = 0.f;

    const int iters = K / KCH;

    uint32_t laneAoff = (uint32_t)((wm*64 + (lane & 15)) * ROWB + ((lane >> 4) & 1) * 16);
    uint32_t laneBoff = (uint32_t)((wn*WN + (lane & 7) + ((lane >= 16) ? 8 : 0)) * ROWB
                                   + ((lane >> 3) & 1) * 16);

    auto load_chunk = [&](int s, int it) {
        int k0 = it * KCH;
        uint32_t sbase = sb + (uint32_t)(s * STAGE);
        #pragma unroll
        for (int i = 0; i < NTASK/256; i++) {
            int task = tid + i * 256;
            if (task < 1024) {
                int r = task >> 3, c = task & 7;
                cp16(sbase + (uint32_t)(r * ROWB + c * 16),
                     A + (size_t)(tileM + r) * lda + k0 + c * 8, 16);
            } else {
                int t2 = task - 1024;
                int r = t2 >> 3, c = t2 & 7;
                int wr = tileN + r;
                const __half* src = W + (size_t)(wr < N ? wr : 0) * ldw + k0 + c * 8;
                cp16(sbase + (uint32_t)(TILEA + r * ROWB + c * 16),
                     src, wr < N ? 16 : 0);
            }
        }
        cp_commit();
    };

    // preload 2 chunks
    if (iters > 0) load_chunk(0, 0);
    if (iters > 1) load_chunk(1, 1);

    for (int it = 0; it < iters; it++) {
        if (iters - 1 - it >= 1) cp_wait<1>();
        else                     cp_wait<0>();
        __syncthreads();
        if (it + 2 < iters) load_chunk((it + 2) % 3, it + 2);

        int s = it % 3;
        uint32_t stA = sb + s*STAGE + laneAoff;
        uint32_t stB = sb + s*STAGE + TILEA + laneBoff;

        #pragma unroll
        for (int ks = 0; ks < 4; ks++) {
            uint32_t a[4][4], b[NBL][4];
            #pragma unroll
            for (int mi = 0; mi < 4; mi++)
                ldsm4(a[mi], stA + mi*16*ROWB + ks*32);
            #pragma unroll
            for (int pi = 0; pi < NBL; pi++)
                ldsm4(b[pi], stB + pi*16*ROWB + ks*32);
            #pragma unroll
            for (int mi = 0; mi < 4; mi++)
                #pragma unroll
                for (int ni = 0; ni < NFR; ni++) {
                    int pi = ni >> 1, j = (ni & 1) * 2;
                    mma16(acc[mi][ni], a[mi], b[pi][j], b[pi][j+1]);
                }
        }
        __syncthreads();
    }

    // ---- epilogue ----
    int g = lane >> 2, t4 = lane & 3;
    int warpN0 = tileN + wn*WN;
    #pragma unroll
    for (int mi = 0; mi < 4; mi++) {
        int r0 = tileM + wm*64 + mi*16 + g;
        #pragma unroll
        for (int ni = 0; ni < NFR; ni++) {
            int c = warpN0 + ni*8 + 2*t4;
            if (c >= N) continue;
            float2 v0 = make_float2(acc[mi][ni][0], acc[mi][ni][1]);
            float2 v1 = make_float2(acc[mi][ni][2], acc[mi][ni][3]);
            float* p0 = C + (size_t)r0 * ldc + c;
            float* p1 = C + (size_t)(r0 + 8) * ldc + c;
            if (EPI == 1) {
                float2 o0 = *(float2*)p0, o1 = *(float2*)p1;
                v0.x += o0.x; v0.y += o0.y; v1.x += o1.x; v1.y += o1.y;
            } else if (EPI == 2) {
                float b0 = bias[c], b1 = bias[c+1];
                v0.x += b0; v0.y += b1; v1.x += b0; v1.y += b1;
                v0.x = (v0.x > 20.f) ? v0.x : log1pf(expf(v0.x));
                v0.y = (v0.y > 20.f) ? v0.y : log1pf(expf(v0.y));
                v1.x = (v1.x > 20.f) ? v1.x : log1pf(expf(v1.x));
                v1.y = (v1.y > 20.f) ? v1.y : log1pf(expf(v1.y));
            }
            *(float2*)p0 = v0;
            *(float2*)p1 = v1;
            if (EPI == 3) {
                *(uint32_t*)(aux + (size_t)r0*ldc + c)     = pack2h(v0.x, v0.y);
                *(uint32_t*)(aux + (size_t)(r0+8)*ldc + c) = pack2h(v1.x, v1.y);
            }
        }
    }
}

#define SMEMB(BN) (3 * (TILEA + (BN)*ROWB))

// ----------------------------------------------------------
extern "C" void kernel_launch(void* const* d_in, const int* in_sizes, int n_in,
                              void* d_out, int out_size)
{
    const int*   tokens       = (const int*)  d_in[0];
    const float* embed        = (const float*)d_in[1];
    const float* norm_w       = (const float*)d_in[2];
    const float* in_proj_w    = (const float*)d_in[3];
    const float* conv_w       = (const float*)d_in[4];
    const float* conv_b       = (const float*)d_in[5];
    const float* x_proj_w     = (const float*)d_in[6];
    const float* dt_w         = (const float*)d_in[7];
    const float* dt_b         = (const float*)d_in[8];
    const float* A_log        = (const float*)d_in[9];
    const float* D_skip       = (const float*)d_in[10];
    const float* out_proj_w   = (const float*)d_in[11];
    const float* final_norm_w = (const float*)d_in[12];
    float* out = (float*)d_out;

    float *h, *xz, *xc, *xdbl, *dts;
    __half *xnf,*xcf,*xdf,*yf;
    __half *winf,*woutf,*wxpf,*wdtf,*wembf;
    cudaGetSymbolAddress((void**)&h,    g_h);
    cudaGetSymbolAddress((void**)&xz,   g_xz);
    cudaGetSymbolAddress((void**)&xc,   g_xc);
    cudaGetSymbolAddress((void**)&xdbl, g_xdbl);
    cudaGetSymbolAddress((void**)&dts,  g_dt);
    cudaGetSymbolAddress((void**)&xnf,  g_xn_f);
    cudaGetSymbolAddress((void**)&xcf,  g_xc_f);
    cudaGetSymbolAddress((void**)&xdf,  g_xd_f);
    cudaGetSymbolAddress((void**)&yf,   g_y_f);
    cudaGetSymbolAddress((void**)&winf, g_win_f);
    cudaGetSymbolAddress((void**)&woutf,g_wout_f);
    cudaGetSymbolAddress((void**)&wxpf, g_wxp_f);
    cudaGetSymbolAddress((void**)&wdtf, g_wdt_f);
    cudaGetSymbolAddress((void**)&wembf,g_wemb_f);

    cudaFuncSetAttribute(mma_gemm<0,256>, cudaFuncAttributeMaxDynamicSharedMemorySize, SMEMB(256));
    cudaFuncSetAttribute(mma_gemm<1,128>, cudaFuncAttributeMaxDynamicSharedMemorySize, SMEMB(128));
    cudaFuncSetAttribute(mma_gemm<2,128>, cudaFuncAttributeMaxDynamicSharedMemorySize, SMEMB(128));
    cudaFuncSetAttribute(mma_gemm<3,128>, cudaFuncAttributeMaxDynamicSharedMemorySize, SMEMB(128));

    // one-pass fp16 conversion of all weights
    {
        int n4;
        n4 = NLAYER*2*DINNER*DMODEL/4; cvt_h_k<<<(n4+255)/256, 256>>>(in_proj_w,  winf,  n4);
        n4 = NLAYER*DMODEL*DINNER/4;   cvt_h_k<<<(n4+255)/256, 256>>>(out_proj_w, woutf, n4);
        n4 = NLAYER*XDBL_W*DINNER/4;   cvt_h_k<<<(n4+255)/256, 256>>>(x_proj_w,   wxpf,  n4);
        n4 = NLAYER*DINNER*DTRANK/4;   cvt_h_k<<<(n4+255)/256, 256>>>(dt_w,       wdtf,  n4);
        n4 = VOCAB*DMODEL/4;           cvt_h_k<<<(n4+255)/256, 256>>>(embed,      wembf, n4);
    }

    embed_k<<<TTOK, 256>>>(tokens, embed, h);

    for (int L = 0; L < NLAYER; L++) {
        rmsnorm_k<<<TTOK, 256>>>(h, norm_w + (size_t)L * DMODEL, xnf);

        // in_proj: [2048,1024] x [4096,1024]^T -> xz (fp32)
        mma_gemm<0,256><<<dim3(2*DINNER/256, TTOK/128), 256, SMEMB(256)>>>(
            xnf, DMODEL, winf + (size_t)L * 2*DINNER*DMODEL, DMODEL,
            xz, 2*DINNER, nullptr, nullptr, 2*DINNER, DMODEL);

        conv_silu_k<<<(TTOK*DINNER + 255)/256, 256>>>(
            xz, conv_w + (size_t)L * DINNER*DCONV, conv_b + (size_t)L * DINNER,
            xc, xcf);

        // x_proj: [2048,2048] x [96,2048]^T -> xdbl (fp32 + fp16 aux)
        mma_gemm<3,128><<<dim3(1, TTOK/128), 256, SMEMB(128)>>>(
            xcf, DINNER, wxpf + (size_t)L * XDBL_W*DINNER, DINNER,
            xdbl, XDBL_W, nullptr, xdf, XDBL_W, DINNER);

        // dt: softplus([2048,96(:64)] x [2048,64]^T + dt_b)
        mma_gemm<2,128><<<dim3(DINNER/128, TTOK/128), 256, SMEMB(128)>>>(
            xdf, XDBL_W, wdtf + (size_t)L * DINNER*DTRANK, DTRANK,
            dts, DINNER, dt_b + (size_t)L * DINNER, nullptr, DINNER, DTRANK);

        scan_k<<<256, 256>>>(xdbl, dts, xc, xz,
                             A_log + (size_t)L * DINNER*DSTATE,
                             D_skip + (size_t)L * DINNER, yf);

        // out_proj (+residual): [2048,2048] x [1024,2048]^T += h
        mma_gemm<1,128><<<dim3(DMODEL/128, TTOK/128), 256, SMEMB(128)>>>(
            yf, DINNER, woutf + (size_t)L * DMODEL*DINNER, DINNER,
            h, DMODEL, nullptr, nullptr, DMODEL, DINNER);
    }

    rmsnorm_k<<<TTOK, 256>>>(h, final_norm_w, xnf);

    // logits: [2048,1024] x [32000,1024]^T
    mma_gemm<0,256><<<dim3(VOCAB/256, TTOK/128), 256, SMEMB(256)>>>(
        xnf, DMODEL, wembf, DMODEL, out, VOCAB, nullptr, nullptr, VOCAB, DMODEL);
}

// round 8
// speedup vs baseline: 1.5618x; 1.1146x over previous
#include <cuda_runtime.h>
#include <cuda_fp16.h>
#include <math.h>
#include <stdint.h>

#define BATCH   2
#define SEQ     1024
#define DMODEL  1024
#define NLAYER  4
#define VOCAB   32000
#define DSTATE  16
#define DCONV   4
#define DINNER  2048
#define DTRANK  64
#define TTOK    (BATCH*SEQ)
#define XDBL_W  96

// -------- fp32 scratch --------
__device__ float g_h   [TTOK*DMODEL];
__device__ float g_xz  [TTOK*2*DINNER];
__device__ float g_xc  [TTOK*DINNER];
__device__ float g_xdbl[TTOK*XDBL_W];
__device__ float g_dt  [TTOK*DINNER];
// -------- fp16 activations --------
__device__ __half g_xn_f[TTOK*DMODEL];
__device__ __half g_xc_f[TTOK*DINNER];
__device__ __half g_xd_f[TTOK*XDBL_W];
__device__ __half g_y_f [TTOK*DINNER];
// -------- fp16 weights --------
__device__ __half g_win_f [NLAYER*2*DINNER*DMODEL];
__device__ __half g_wout_f[NLAYER*DMODEL*DINNER];
__device__ __half g_wxp_f [NLAYER*XDBL_W*DINNER];
__device__ __half g_wdt_f [NLAYER*DINNER*DTRANK];
__device__ __half g_wemb_f[VOCAB*DMODEL];

// ---------------- helpers ----------------
__device__ __forceinline__ void cp16(uint32_t dst, const void* src, int srcBytes) {
    asm volatile("cp.async.cg.shared.global [%0], [%1], 16, %2;"
                 :: "r"(dst), "l"(src), "r"(srcBytes));
}
__device__ __forceinline__ void cp_commit() { asm volatile("cp.async.commit_group;"); }
template<int N> __device__ __forceinline__ void cp_wait() {
    asm volatile("cp.async.wait_group %0;" :: "n"(N));
}
__device__ __forceinline__ void ldsm4(uint32_t* r, uint32_t addr) {
    asm volatile("ldmatrix.sync.aligned.m8n8.x4.shared.b16 {%0,%1,%2,%3}, [%4];"
                 : "=r"(r[0]), "=r"(r[1]), "=r"(r[2]), "=r"(r[3]) : "r"(addr));
}
__device__ __forceinline__ void mma16(float* d, const uint32_t* a, uint32_t b0, uint32_t b1) {
    asm volatile(
        "mma.sync.aligned.m16n8k16.row.col.f32.f16.f16.f32 "
        "{%0,%1,%2,%3}, {%4,%5,%6,%7}, {%8,%9}, {%0,%1,%2,%3};\n"
        : "+f"(d[0]), "+f"(d[1]), "+f"(d[2]), "+f"(d[3])
        : "r"(a[0]), "r"(a[1]), "r"(a[2]), "r"(a[3]), "r"(b0), "r"(b1));
}
__device__ __forceinline__ uint32_t pack2h(float a, float b) {
    __half2 p = __floats2half2_rn(a, b);
    return *(uint32_t*)&p;
}

// ---------------- elementwise kernels ----------------
// single launch: convert all 5 weight tensors to fp16
__global__ void cvt_all_k(const float* __restrict__ s0, __half* __restrict__ d0, int n0,
                          const float* __restrict__ s1, __half* __restrict__ d1, int n1,
                          const float* __restrict__ s2, __half* __restrict__ d2, int n2,
                          const float* __restrict__ s3, __half* __restrict__ d3, int n3,
                          const float* __restrict__ s4, __half* __restrict__ d4, int n4)
{
    int i = blockIdx.x * blockDim.x + threadIdx.x;
    const float* s; __half* d; int j = i;
    if (i < n0)                       { s = s0; d = d0; }
    else if ((j -= n0) < n1)          { s = s1; d = d1; }
    else if ((j -= n1) < n2)          { s = s2; d = d2; }
    else if ((j -= n2) < n3)          { s = s3; d = d3; }
    else if ((j -= n3) < n4)          { s = s4; d = d4; }
    else return;
    float4 v = ((const float4*)s)[j];
    uint2 p;
    p.x = pack2h(v.x, v.y);
    p.y = pack2h(v.z, v.w);
    ((uint2*)d)[j] = p;
}

__global__ void embed_k(const int* __restrict__ tok, const float* __restrict__ emb,
                        float* __restrict__ out)
{
    int t = blockIdx.x;
    int row = tok[t];
    ((float4*)(out + (size_t)t * DMODEL))[threadIdx.x] =
        ((const float4*)(emb + (size_t)row * DMODEL))[threadIdx.x];
}

__global__ void rmsnorm_k(const float* __restrict__ x, const float* __restrict__ w,
                          __half* __restrict__ oh)
{
    int t = blockIdx.x;
    int tid = threadIdx.x;
    float4 v = ((const float4*)(x + (size_t)t * DMODEL))[tid];
    float ss = v.x*v.x + v.y*v.y + v.z*v.z + v.w*v.w;
    __shared__ float sbuf[8];
    #pragma unroll
    for (int o = 16; o; o >>= 1) ss += __shfl_xor_sync(0xffffffffu, ss, o);
    int warp = tid >> 5, lane = tid & 31;
    if (lane == 0) sbuf[warp] = ss;
    __syncthreads();
    if (warp == 0) {
        float s2 = (lane < 8) ? sbuf[lane] : 0.f;
        #pragma unroll
        for (int o = 4; o; o >>= 1) s2 += __shfl_xor_sync(0xffffffffu, s2, o);
        if (lane == 0) sbuf[0] = rsqrtf(s2 * (1.0f / DMODEL) + 1e-5f);
    }
    __syncthreads();
    float r = sbuf[0];
    float4 wv = ((const float4*)w)[tid];
    uint2 p;
    p.x = pack2h(v.x*r*wv.x, v.y*r*wv.y);
    p.y = pack2h(v.z*r*wv.z, v.w*r*wv.w);
    ((uint2*)(oh + (size_t)t * DMODEL))[tid] = p;
}

__global__ void conv_silu_k(const float* __restrict__ xz, const float* __restrict__ cw,
                            const float* __restrict__ cb, float* __restrict__ xc,
                            __half* __restrict__ xch)
{
    int idx = blockIdx.x * blockDim.x + threadIdx.x;
    if (idx >= TTOK * DINNER) return;
    int c = idx % DINNER;
    int t = idx / DINNER;
    int l = t % SEQ;
    float4 w4 = *(const float4*)(cw + c * 4);
    const size_t str = 2 * DINNER;
    float acc = cb[c];
    if (l >= 3) acc += w4.x * xz[(size_t)(t-3)*str + c];
    if (l >= 2) acc += w4.y * xz[(size_t)(t-2)*str + c];
    if (l >= 1) acc += w4.z * xz[(size_t)(t-1)*str + c];
    acc += w4.w * xz[(size_t)t*str + c];
    float s = 1.f / (1.f + expf(-acc));
    float o = acc * s;
    xc[idx] = o;
    xch[idx] = __float2half_rn(o);
}

// selective scan, software-pipelined loads (prefetch t+1 before computing t)
__global__ __launch_bounds__(256)
void scan_k(const float* __restrict__ xdbl, const float* __restrict__ dt,
            const float* __restrict__ xc,   const float* __restrict__ xz,
            const float* __restrict__ A_log, const float* __restrict__ Dsk,
            __half* __restrict__ yh)
{
    int s = threadIdx.x & 15;
    int c = ((blockIdx.x & 127) << 4) + (threadIdx.x >> 4);
    int b = blockIdx.x >> 7;
    float A = -expf(A_log[(size_t)c * DSTATE + s]);
    float dval = Dsk[c];
    bool lane0 = (s == 0);
    float h = 0.f;
    int tbase = b * SEQ;

    int t = tbase;
    float dtv = dt  [(size_t)t * DINNER + c];
    float xv  = xc  [(size_t)t * DINNER + c];
    float Bv  = xdbl[(size_t)t * XDBL_W + DTRANK + s];
    float Cv  = xdbl[(size_t)t * XDBL_W + DTRANK + DSTATE + s];

    for (int l = 0; l < SEQ; l++, t++) {
        // prefetch next step's operands (independent of recurrence)
        int tn = (l + 1 < SEQ) ? t + 1 : t;
        float dt2 = dt  [(size_t)tn * DINNER + c];
        float x2  = xc  [(size_t)tn * DINNER + c];
        float B2  = xdbl[(size_t)tn * XDBL_W + DTRANK + s];
        float C2  = xdbl[(size_t)tn * XDBL_W + DTRANK + DSTATE + s];

        float dA = __expf(dtv * A);
        h = dA * h + (dtv * xv) * Bv;
        float p = h * Cv;
        p += __shfl_xor_sync(0xffffffffu, p, 8);
        p += __shfl_xor_sync(0xffffffffu, p, 4);
        p += __shfl_xor_sync(0xffffffffu, p, 2);
        p += __shfl_xor_sync(0xffffffffu, p, 1);
        if (lane0) {
            float z = xz[(size_t)t * (2*DINNER) + DINNER + c];
            float sg = 1.f / (1.f + __expf(-z));
            yh[(size_t)t * DINNER + c] = __float2half_rn((p + dval * xv) * (z * sg));
        }
        dtv = dt2; xv = x2; Bv = B2; Cv = C2;
    }
}

// ----------------------------------------------------------
// FP16 HMMA GEMM (NT): C[2048,N] = A[2048,K] x W[N,K]^T
// CTA 128xBN, 8 warps (2M x 4N), warp tile 64x(BN/4), KCH=64.
// Rows 144B -> conflict-free ldmatrix. 3-stage cp.async.
// MB = min blocks/SM (2 for BN=128 -> 16 warps/SM).
// EPI: 0=store 1=accum 2=softplus+bias 3=store+fp16aux
// ----------------------------------------------------------
#define KCH     64
#define ROWB    144
#define TILEA   (128*ROWB)

template<int EPI, int BN, int MB>
__global__ __launch_bounds__(256, MB)
void mma_gemm(const __half* __restrict__ A, int lda,
              const __half* __restrict__ W, int ldw,
              float* __restrict__ C, int ldc,
              const float* __restrict__ bias,
              __half* __restrict__ aux,
              int N, int K)
{
    constexpr int WN    = BN / 4;
    constexpr int NFR   = WN / 8;
    constexpr int NBL   = WN / 16;
    constexpr int TILEB = BN * ROWB;
    constexpr int STAGE = TILEA + TILEB;
    constexpr int NTASK = (128 + BN) * 8;

    extern __shared__ char smem[];
    uint32_t sb = (uint32_t)__cvta_generic_to_shared(smem);

    int tid = threadIdx.x, lane = tid & 31, warp = tid >> 5;
    int wm = warp & 1;
    int wn = warp >> 1;
    int tileM = blockIdx.y * 128, tileN = blockIdx.x * BN;

    float acc[4][NFR][4];
    #pragma unroll
    for (int mi = 0; mi < 4; mi++)
        #pragma unroll
        for (int ni = 0; ni < NFR; ni++)
            #pragma unroll
            for (int e = 0; e < 4; e++) acc[mi][ni][e] = 0.f;

    const int iters = K / KCH;

    uint32_t laneAoff = (uint32_t)((wm*64 + (lane & 15)) * ROWB + ((lane >> 4) & 1) * 16);
    uint32_t laneBoff = (uint32_t)((wn*WN + (lane & 7) + ((lane >= 16) ? 8 : 0)) * ROWB
                                   + ((lane >> 3) & 1) * 16);

    auto load_chunk = [&](int s, int it) {
        int k0 = it * KCH;
        uint32_t sbase = sb + (uint32_t)(s * STAGE);
        #pragma unroll
        for (int i = 0; i < NTASK/256; i++) {
            int task = tid + i * 256;
            if (task < 1024) {
                int r = task >> 3, c = task & 7;
                cp16(sbase + (uint32_t)(r * ROWB + c * 16),
                     A + (size_t)(tileM + r) * lda + k0 + c * 8, 16);
            } else {
                int t2 = task - 1024;
                int r = t2 >> 3, c = t2 & 7;
                int wr = tileN + r;
                const __half* src = W + (size_t)(wr < N ? wr : 0) * ldw + k0 + c * 8;
                cp16(sbase + (uint32_t)(TILEA + r * ROWB + c * 16),
                     src, wr < N ? 16 : 0);
            }
        }
        cp_commit();
    };

    if (iters > 0) load_chunk(0, 0);
    if (iters > 1) load_chunk(1, 1);

    for (int it = 0; it < iters; it++) {
        if (iters - 1 - it >= 1) cp_wait<1>();
        else                     cp_wait<0>();
        __syncthreads();
        if (it + 2 < iters) load_chunk((it + 2) % 3, it + 2);

        int s = it % 3;
        uint32_t stA = sb + s*STAGE + laneAoff;
        uint32_t stB = sb + s*STAGE + TILEA + laneBoff;

        #pragma unroll
        for (int ks = 0; ks < 4; ks++) {
            uint32_t a[4][4], b[NBL][4];
            #pragma unroll
            for (int mi = 0; mi < 4; mi++)
                ldsm4(a[mi], stA + mi*16*ROWB + ks*32);
            #pragma unroll
            for (int pi = 0; pi < NBL; pi++)
                ldsm4(b[pi], stB + pi*16*ROWB + ks*32);
            #pragma unroll
            for (int mi = 0; mi < 4; mi++)
                #pragma unroll
                for (int ni = 0; ni < NFR; ni++) {
                    int pi = ni >> 1, j = (ni & 1) * 2;
                    mma16(acc[mi][ni], a[mi], b[pi][j], b[pi][j+1]);
                }
        }
        __syncthreads();
    }

    // ---- epilogue ----
    int g = lane >> 2, t4 = lane & 3;
    int warpN0 = tileN + wn*WN;
    #pragma unroll
    for (int mi = 0; mi < 4; mi++) {
        int r0 = tileM + wm*64 + mi*16 + g;
        #pragma unroll
        for (int ni = 0; ni < NFR; ni++) {
            int c = warpN0 + ni*8 + 2*t4;
            if (c >= N) continue;
            float2 v0 = make_float2(acc[mi][ni][0], acc[mi][ni][1]);
            float2 v1 = make_float2(acc[mi][ni][2], acc[mi][ni][3]);
            float* p0 = C + (size_t)r0 * ldc + c;
            float* p1 = C + (size_t)(r0 + 8) * ldc + c;
            if (EPI == 1) {
                float2 o0 = *(float2*)p0, o1 = *(float2*)p1;
                v0.x += o0.x; v0.y += o0.y; v1.x += o1.x; v1.y += o1.y;
            } else if (EPI == 2) {
                float b0 = bias[c], b1 = bias[c+1];
                v0.x += b0; v0.y += b1; v1.x += b0; v1.y += b1;
                v0.x = (v0.x > 20.f) ? v0.x : log1pf(expf(v0.x));
                v0.y = (v0.y > 20.f) ? v0.y : log1pf(expf(v0.y));
                v1.x = (v1.x > 20.f) ? v1.x : log1pf(expf(v1.x));
                v1.y = (v1.y > 20.f) ? v1.y : log1pf(expf(v1.y));
            }
            *(float2*)p0 = v0;
            *(float2*)p1 = v1;
            if (EPI == 3) {
                *(uint32_t*)(aux + (size_t)r0*ldc + c)     = pack2h(v0.x, v0.y);
                *(uint32_t*)(aux + (size_t)(r0+8)*ldc + c) = pack2h(v1.x, v1.y);
            }
        }
    }
}

#define SMEMB(BN) (3 * (TILEA + (BN)*ROWB))

// ----------------------------------------------------------
extern "C" void kernel_launch(void* const* d_in, const int* in_sizes, int n_in,
                              void* d_out, int out_size)
{
    const int*   tokens       = (const int*)  d_in[0];
    const float* embed        = (const float*)d_in[1];
    const float* norm_w       = (const float*)d_in[2];
    const float* in_proj_w    = (const float*)d_in[3];
    const float* conv_w       = (const float*)d_in[4];
    const float* conv_b       = (const float*)d_in[5];
    const float* x_proj_w     = (const float*)d_in[6];
    const float* dt_w         = (const float*)d_in[7];
    const float* dt_b         = (const float*)d_in[8];
    const float* A_log        = (const float*)d_in[9];
    const float* D_skip       = (const float*)d_in[10];
    const float* out_proj_w   = (const float*)d_in[11];
    const float* final_norm_w = (const float*)d_in[12];
    float* out = (float*)d_out;

    float *h, *xz, *xc, *xdbl, *dts;
    __half *xnf,*xcf,*xdf,*yf;
    __half *winf,*woutf,*wxpf,*wdtf,*wembf;
    cudaGetSymbolAddress((void**)&h,    g_h);
    cudaGetSymbolAddress((void**)&xz,   g_xz);
    cudaGetSymbolAddress((void**)&xc,   g_xc);
    cudaGetSymbolAddress((void**)&xdbl, g_xdbl);
    cudaGetSymbolAddress((void**)&dts,  g_dt);
    cudaGetSymbolAddress((void**)&xnf,  g_xn_f);
    cudaGetSymbolAddress((void**)&xcf,  g_xc_f);
    cudaGetSymbolAddress((void**)&xdf,  g_xd_f);
    cudaGetSymbolAddress((void**)&yf,   g_y_f);
    cudaGetSymbolAddress((void**)&winf, g_win_f);
    cudaGetSymbolAddress((void**)&woutf,g_wout_f);
    cudaGetSymbolAddress((void**)&wxpf, g_wxp_f);
    cudaGetSymbolAddress((void**)&wdtf, g_wdt_f);
    cudaGetSymbolAddress((void**)&wembf,g_wemb_f);

    cudaFuncSetAttribute((const void*)mma_gemm<0,256,1>, cudaFuncAttributeMaxDynamicSharedMemorySize, SMEMB(256));
    cudaFuncSetAttribute((const void*)mma_gemm<1,128,2>, cudaFuncAttributeMaxDynamicSharedMemorySize, SMEMB(128));
    cudaFuncSetAttribute((const void*)mma_gemm<2,128,2>, cudaFuncAttributeMaxDynamicSharedMemorySize, SMEMB(128));
    cudaFuncSetAttribute((const void*)mma_gemm<3,128,2>, cudaFuncAttributeMaxDynamicSharedMemorySize, SMEMB(128));

    // launch 0: ALL weight conversions (one kernel)
    {
        int n0 = NLAYER*2*DINNER*DMODEL/4;
        int n1 = NLAYER*DMODEL*DINNER/4;
        int n2 = NLAYER*XDBL_W*DINNER/4;
        int n3 = NLAYER*DINNER*DTRANK/4;
        int n4 = VOCAB*DMODEL/4;
        int tot = n0 + n1 + n2 + n3 + n4;
        cvt_all_k<<<(tot+255)/256, 256>>>(in_proj_w, winf, n0,
                                          out_proj_w, woutf, n1,
                                          x_proj_w,  wxpf,  n2,
                                          dt_w,      wdtf,  n3,
                                          embed,     wembf, n4);
    }

    embed_k<<<TTOK, 256>>>(tokens, embed, h);                       // launch 1

    for (int L = 0; L < NLAYER; L++) {
        rmsnorm_k<<<TTOK, 256>>>(h, norm_w + (size_t)L * DMODEL, xnf);   // launch 2 (L=0)

        // launch 3 (L=0): in_proj — ncu capture slot
        mma_gemm<0,256,1><<<dim3(2*DINNER/256, TTOK/128), 256, SMEMB(256)>>>(
            xnf, DMODEL, winf + (size_t)L * 2*DINNER*DMODEL, DMODEL,
            xz, 2*DINNER, nullptr, nullptr, 2*DINNER, DMODEL);

        conv_silu_k<<<(TTOK*DINNER + 255)/256, 256>>>(
            xz, conv_w + (size_t)L * DINNER*DCONV, conv_b + (size_t)L * DINNER,
            xc, xcf);

        mma_gemm<3,128,2><<<dim3(1, TTOK/128), 256, SMEMB(128)>>>(
            xcf, DINNER, wxpf + (size_t)L * XDBL_W*DINNER, DINNER,
            xdbl, XDBL_W, nullptr, xdf, XDBL_W, DINNER);

        mma_gemm<2,128,2><<<dim3(DINNER/128, TTOK/128), 256, SMEMB(128)>>>(
            xdf, XDBL_W, wdtf + (size_t)L * DINNER*DTRANK, DTRANK,
            dts, DINNER, dt_b + (size_t)L * DINNER, nullptr, DINNER, DTRANK);

        scan_k<<<256, 256>>>(xdbl, dts, xc, xz,
                             A_log + (size_t)L * DINNER*DSTATE,
                             D_skip + (size_t)L * DINNER, yf);

        mma_gemm<1,128,2><<<dim3(DMODEL/128, TTOK/128), 256, SMEMB(128)>>>(
            yf, DINNER, woutf + (size_t)L * DMODEL*DINNER, DINNER,
            h, DMODEL, nullptr, nullptr, DMODEL, DINNER);
    }

    rmsnorm_k<<<TTOK, 256>>>(h, final_norm_w, xnf);

    mma_gemm<0,256,1><<<dim3(VOCAB/256, TTOK/128), 256, SMEMB(256)>>>(
        xnf, DMODEL, wembf, DMODEL, out, VOCAB, nullptr, nullptr, VOCAB, DMODEL);
}

// round 9
// speedup vs baseline: 1.5843x; 1.0144x over previous
#include <cuda_runtime.h>
#include <cuda_fp16.h>
#include <math.h>
#include <stdint.h>

#define BATCH   2
#define SEQ     1024
#define DMODEL  1024
#define NLAYER  4
#define VOCAB   32000
#define DSTATE  16
#define DCONV   4
#define DINNER  2048
#define DTRANK  64
#define TTOK    (BATCH*SEQ)
#define XDBL_W  96

// -------- fp32 scratch --------
__device__ float g_h   [TTOK*DMODEL];
__device__ float g_xz  [TTOK*2*DINNER];
__device__ float g_xc  [TTOK*DINNER];
__device__ float g_xdbl[TTOK*XDBL_W];
__device__ float g_dt  [TTOK*DINNER];
// -------- fp16 activations --------
__device__ __half g_xn_f[TTOK*DMODEL];
__device__ __half g_xc_f[TTOK*DINNER];
__device__ __half g_xd_f[TTOK*XDBL_W];
__device__ __half g_y_f [TTOK*DINNER];
// -------- fp16 weights --------
__device__ __half g_win_f [NLAYER*2*DINNER*DMODEL];
__device__ __half g_wout_f[NLAYER*DMODEL*DINNER];
__device__ __half g_wxp_f [NLAYER*XDBL_W*DINNER];
__device__ __half g_wdt_f [NLAYER*DINNER*DTRANK];
__device__ __half g_wemb_f[VOCAB*DMODEL];

// ---------------- helpers ----------------
__device__ __forceinline__ void cp16(uint32_t dst, const void* src, int srcBytes) {
    asm volatile("cp.async.cg.shared.global [%0], [%1], 16, %2;"
                 :: "r"(dst), "l"(src), "r"(srcBytes));
}
__device__ __forceinline__ void cp_commit() { asm volatile("cp.async.commit_group;"); }
template<int N> __device__ __forceinline__ void cp_wait() {
    asm volatile("cp.async.wait_group %0;" :: "n"(N));
}
__device__ __forceinline__ void ldsm4(uint32_t* r, uint32_t addr) {
    asm volatile("ldmatrix.sync.aligned.m8n8.x4.shared.b16 {%0,%1,%2,%3}, [%4];"
                 : "=r"(r[0]), "=r"(r[1]), "=r"(r[2]), "=r"(r[3]) : "r"(addr));
}
__device__ __forceinline__ void mma16(float* d, const uint32_t* a, uint32_t b0, uint32_t b1) {
    asm volatile(
        "mma.sync.aligned.m16n8k16.row.col.f32.f16.f16.f32 "
        "{%0,%1,%2,%3}, {%4,%5,%6,%7}, {%8,%9}, {%0,%1,%2,%3};\n"
        : "+f"(d[0]), "+f"(d[1]), "+f"(d[2]), "+f"(d[3])
        : "r"(a[0]), "r"(a[1]), "r"(a[2]), "r"(a[3]), "r"(b0), "r"(b1));
}
__device__ __forceinline__ uint32_t pack2h(float a, float b) {
    __half2 p = __floats2half2_rn(a, b);
    return *(uint32_t*)&p;
}

// ---------------- elementwise kernels ----------------
__global__ void cvt_all_k(const float* __restrict__ s0, __half* __restrict__ d0, int n0,
                          const float* __restrict__ s1, __half* __restrict__ d1, int n1,
                          const float* __restrict__ s2, __half* __restrict__ d2, int n2,
                          const float* __restrict__ s3, __half* __restrict__ d3, int n3,
                          const float* __restrict__ s4, __half* __restrict__ d4, int n4)
{
    int i = blockIdx.x * blockDim.x + threadIdx.x;
    const float* s; __half* d; int j = i;
    if (i < n0)                       { s = s0; d = d0; }
    else if ((j -= n0) < n1)          { s = s1; d = d1; }
    else if ((j -= n1) < n2)          { s = s2; d = d2; }
    else if ((j -= n2) < n3)          { s = s3; d = d3; }
    else if ((j -= n3) < n4)          { s = s4; d = d4; }
    else return;
    float4 v = ((const float4*)s)[j];
    uint2 p;
    p.x = pack2h(v.x, v.y);
    p.y = pack2h(v.z, v.w);
    ((uint2*)d)[j] = p;
}

__global__ void embed_k(const int* __restrict__ tok, const float* __restrict__ emb,
                        float* __restrict__ out)
{
    int t = blockIdx.x;
    int row = tok[t];
    ((float4*)(out + (size_t)t * DMODEL))[threadIdx.x] =
        ((const float4*)(emb + (size_t)row * DMODEL))[threadIdx.x];
}

__global__ void rmsnorm_k(const float* __restrict__ x, const float* __restrict__ w,
                          __half* __restrict__ oh)
{
    int t = blockIdx.x;
    int tid = threadIdx.x;
    float4 v = ((const float4*)(x + (size_t)t * DMODEL))[tid];
    float ss = v.x*v.x + v.y*v.y + v.z*v.z + v.w*v.w;
    __shared__ float sbuf[8];
    #pragma unroll
    for (int o = 16; o; o >>= 1) ss += __shfl_xor_sync(0xffffffffu, ss, o);
    int warp = tid >> 5, lane = tid & 31;
    if (lane == 0) sbuf[warp] = ss;
    __syncthreads();
    if (warp == 0) {
        float s2 = (lane < 8) ? sbuf[lane] : 0.f;
        #pragma unroll
        for (int o = 4; o; o >>= 1) s2 += __shfl_xor_sync(0xffffffffu, s2, o);
        if (lane == 0) sbuf[0] = rsqrtf(s2 * (1.0f / DMODEL) + 1e-5f);
    }
    __syncthreads();
    float r = sbuf[0];
    float4 wv = ((const float4*)w)[tid];
    uint2 p;
    p.x = pack2h(v.x*r*wv.x, v.y*r*wv.y);
    p.y = pack2h(v.z*r*wv.z, v.w*r*wv.w);
    ((uint2*)(oh + (size_t)t * DMODEL))[tid] = p;
}

__global__ void conv_silu_k(const float* __restrict__ xz, const float* __restrict__ cw,
                            const float* __restrict__ cb, float* __restrict__ xc,
                            __half* __restrict__ xch)
{
    int idx = blockIdx.x * blockDim.x + threadIdx.x;
    if (idx >= TTOK * DINNER) return;
    int c = idx % DINNER;
    int t = idx / DINNER;
    int l = t % SEQ;
    float4 w4 = *(const float4*)(cw + c * 4);
    const size_t str = 2 * DINNER;
    float acc = cb[c];
    if (l >= 3) acc += w4.x * xz[(size_t)(t-3)*str + c];
    if (l >= 2) acc += w4.y * xz[(size_t)(t-2)*str + c];
    if (l >= 1) acc += w4.z * xz[(size_t)(t-1)*str + c];
    acc += w4.w * xz[(size_t)t*str + c];
    float s = 1.f / (1.f + expf(-acc));
    float o = acc * s;
    xc[idx] = o;
    xch[idx] = __float2half_rn(o);
}

__global__ __launch_bounds__(256)
void scan_k(const float* __restrict__ xdbl, const float* __restrict__ dt,
            const float* __restrict__ xc,   const float* __restrict__ xz,
            const float* __restrict__ A_log, const float* __restrict__ Dsk,
            __half* __restrict__ yh)
{
    int s = threadIdx.x & 15;
    int c = ((blockIdx.x & 127) << 4) + (threadIdx.x >> 4);
    int b = blockIdx.x >> 7;
    float A = -expf(A_log[(size_t)c * DSTATE + s]);
    float dval = Dsk[c];
    bool lane0 = (s == 0);
    float h = 0.f;
    int tbase = b * SEQ;

    int t = tbase;
    float dtv = dt  [(size_t)t * DINNER + c];
    float xv  = xc  [(size_t)t * DINNER + c];
    float Bv  = xdbl[(size_t)t * XDBL_W + DTRANK + s];
    float Cv  = xdbl[(size_t)t * XDBL_W + DTRANK + DSTATE + s];

    for (int l = 0; l < SEQ; l++, t++) {
        int tn = (l + 1 < SEQ) ? t + 1 : t;
        float dt2 = dt  [(size_t)tn * DINNER + c];
        float x2  = xc  [(size_t)tn * DINNER + c];
        float B2  = xdbl[(size_t)tn * XDBL_W + DTRANK + s];
        float C2  = xdbl[(size_t)tn * XDBL_W + DTRANK + DSTATE + s];

        float dA = __expf(dtv * A);
        h = dA * h + (dtv * xv) * Bv;
        float p = h * Cv;
        p += __shfl_xor_sync(0xffffffffu, p, 8);
        p += __shfl_xor_sync(0xffffffffu, p, 4);
        p += __shfl_xor_sync(0xffffffffu, p, 2);
        p += __shfl_xor_sync(0xffffffffu, p, 1);
        if (lane0) {
            float z = xz[(size_t)t * (2*DINNER) + DINNER + c];
            float sg = 1.f / (1.f + __expf(-z));
            yh[(size_t)t * DINNER + c] = __float2half_rn((p + dval * xv) * (z * sg));
        }
        dtv = dt2; xv = x2; Bv = B2; Cv = C2;
    }
}

// ----------------------------------------------------------
// FP16 HMMA GEMM (NT): C[T,N] = A[T,K] x W[N,K]^T
// CTA BMxBN, 8 warps: WM=BM/64 M-warps x (8/WM) N-warps, warp tile 64x WN.
// KCH=64, rows 144B (conflict-free ldmatrix), 3-stage cp.async, MB CTAs/SM.
// EPI: 0=store 1=accum 2=softplus+bias 3=store+fp16aux
// ----------------------------------------------------------
#define KCH     64
#define ROWB    144

template<int EPI, int BM, int BN, int MB>
__global__ __launch_bounds__(256, MB)
void mma_gemm(const __half* __restrict__ A, int lda,
              const __half* __restrict__ W, int ldw,
              float* __restrict__ C, int ldc,
              const float* __restrict__ bias,
              __half* __restrict__ aux,
              int N, int K)
{
    constexpr int WM    = BM / 64;         // M-warps (1 or 2)
    constexpr int WNW   = 8 / WM;          // N-warps
    constexpr int WN    = BN / WNW;        // warp N tile
    constexpr int NFR   = WN / 8;
    constexpr int NBL   = WN / 16;
    constexpr int TILEA = BM * ROWB;
    constexpr int TILEB = BN * ROWB;
    constexpr int STAGE = TILEA + TILEB;
    constexpr int NTASK = (BM + BN) * 8;

    extern __shared__ char smem[];
    uint32_t sb = (uint32_t)__cvta_generic_to_shared(smem);

    int tid = threadIdx.x, lane = tid & 31, warp = tid >> 5;
    int wm = warp % WM;
    int wn = warp / WM;
    int tileM = blockIdx.y * BM, tileN = blockIdx.x * BN;

    float acc[4][NFR][4];
    #pragma unroll
    for (int mi = 0; mi < 4; mi++)
        #pragma unroll
        for (int ni = 0; ni < NFR; ni++)
            #pragma unroll
            for (int e = 0; e < 4; e++) acc[mi][ni][e] = 0.f;

    const int iters = K / KCH;

    uint32_t laneAoff = (uint32_t)((wm*64 + (lane & 15)) * ROWB + ((lane >> 4) & 1) * 16);
    uint32_t laneBoff = (uint32_t)((wn*WN + (lane & 7) + ((lane >= 16) ? 8 : 0)) * ROWB
                                   + ((lane >> 3) & 1) * 16);

    auto load_chunk = [&](int s, int it) {
        int k0 = it * KCH;
        uint32_t sbase = sb + (uint32_t)(s * STAGE);
        #pragma unroll
        for (int i = 0; i < NTASK/256; i++) {
            int task = tid + i * 256;
            if (task < BM*8) {
                int r = task >> 3, c = task & 7;
                cp16(sbase + (uint32_t)(r * ROWB + c * 16),
                     A + (size_t)(tileM + r) * lda + k0 + c * 8, 16);
            } else {
                int t2 = task - BM*8;
                int r = t2 >> 3, c = t2 & 7;
                int wr = tileN + r;
                const __half* src = W + (size_t)(wr < N ? wr : 0) * ldw + k0 + c * 8;
                cp16(sbase + (uint32_t)(TILEA + r * ROWB + c * 16),
                     src, wr < N ? 16 : 0);
            }
        }
        cp_commit();
    };

    if (iters > 0) load_chunk(0, 0);
    if (iters > 1) load_chunk(1, 1);

    for (int it = 0; it < iters; it++) {
        if (iters - 1 - it >= 1) cp_wait<1>();
        else                     cp_wait<0>();
        __syncthreads();
        if (it + 2 < iters) load_chunk((it + 2) % 3, it + 2);

        int s = it % 3;
        uint32_t stA = sb + s*STAGE + laneAoff;
        uint32_t stB = sb + s*STAGE + TILEA + laneBoff;

        #pragma unroll
        for (int ks = 0; ks < 4; ks++) {
            uint32_t a[4][4], b[NBL][4];
            #pragma unroll
            for (int mi = 0; mi < 4; mi++)
                ldsm4(a[mi], stA + mi*16*ROWB + ks*32);
            #pragma unroll
            for (int pi = 0; pi < NBL; pi++)
                ldsm4(b[pi], stB + pi*16*ROWB + ks*32);
            #pragma unroll
            for (int mi = 0; mi < 4; mi++)
                #pragma unroll
                for (int ni = 0; ni < NFR; ni++) {
                    int pi = ni >> 1, j = (ni & 1) * 2;
                    mma16(acc[mi][ni], a[mi], b[pi][j], b[pi][j+1]);
                }
        }
        __syncthreads();
    }

    // ---- epilogue ----
    int g = lane >> 2, t4 = lane & 3;
    int warpN0 = tileN + wn*WN;
    #pragma unroll
    for (int mi = 0; mi < 4; mi++) {
        int r0 = tileM + wm*64 + mi*16 + g;
        #pragma unroll
        for (int ni = 0; ni < NFR; ni++) {
            int c = warpN0 + ni*8 + 2*t4;
            if (c >= N) continue;
            float2 v0 = make_float2(acc[mi][ni][0], acc[mi][ni][1]);
            float2 v1 = make_float2(acc[mi][ni][2], acc[mi][ni][3]);
            float* p0 = C + (size_t)r0 * ldc + c;
            float* p1 = C + (size_t)(r0 + 8) * ldc + c;
            if (EPI == 1) {
                float2 o0 = *(float2*)p0, o1 = *(float2*)p1;
                v0.x += o0.x; v0.y += o0.y; v1.x += o1.x; v1.y += o1.y;
            } else if (EPI == 2) {
                float b0 = bias[c], b1 = bias[c+1];
                v0.x += b0; v0.y += b1; v1.x += b0; v1.y += b1;
                v0.x = (v0.x > 20.f) ? v0.x : log1pf(expf(v0.x));
                v0.y = (v0.y > 20.f) ? v0.y : log1pf(expf(v0.y));
                v1.x = (v1.x > 20.f) ? v1.x : log1pf(expf(v1.x));
                v1.y = (v1.y > 20.f) ? v1.y : log1pf(expf(v1.y));
            }
            *(float2*)p0 = v0;
            *(float2*)p1 = v1;
            if (EPI == 3) {
                *(uint32_t*)(aux + (size_t)r0*ldc + c)     = pack2h(v0.x, v0.y);
                *(uint32_t*)(aux + (size_t)(r0+8)*ldc + c) = pack2h(v1.x, v1.y);
            }
        }
    }
}

#define SMEMB(BM,BN) (3 * ((BM) + (BN)) * ROWB)

// ----------------------------------------------------------
extern "C" void kernel_launch(void* const* d_in, const int* in_sizes, int n_in,
                              void* d_out, int out_size)
{
    const int*   tokens       = (const int*)  d_in[0];
    const float* embed        = (const float*)d_in[1];
    const float* norm_w       = (const float*)d_in[2];
    const float* in_proj_w    = (const float*)d_in[3];
    const float* conv_w       = (const float*)d_in[4];
    const float* conv_b       = (const float*)d_in[5];
    const float* x_proj_w     = (const float*)d_in[6];
    const float* dt_w         = (const float*)d_in[7];
    const float* dt_b         = (const float*)d_in[8];
    const float* A_log        = (const float*)d_in[9];
    const float* D_skip       = (const float*)d_in[10];
    const float* out_proj_w   = (const float*)d_in[11];
    const float* final_norm_w = (const float*)d_in[12];
    float* out = (float*)d_out;

    float *h, *xz, *xc, *xdbl, *dts;
    __half *xnf,*xcf,*xdf,*yf;
    __half *winf,*woutf,*wxpf,*wdtf,*wembf;
    cudaGetSymbolAddress((void**)&h,    g_h);
    cudaGetSymbolAddress((void**)&xz,   g_xz);
    cudaGetSymbolAddress((void**)&xc,   g_xc);
    cudaGetSymbolAddress((void**)&xdbl, g_xdbl);
    cudaGetSymbolAddress((void**)&dts,  g_dt);
    cudaGetSymbolAddress((void**)&xnf,  g_xn_f);
    cudaGetSymbolAddress((void**)&xcf,  g_xc_f);
    cudaGetSymbolAddress((void**)&xdf,  g_xd_f);
    cudaGetSymbolAddress((void**)&yf,   g_y_f);
    cudaGetSymbolAddress((void**)&winf, g_win_f);
    cudaGetSymbolAddress((void**)&woutf,g_wout_f);
    cudaGetSymbolAddress((void**)&wxpf, g_wxp_f);
    cudaGetSymbolAddress((void**)&wdtf, g_wdt_f);
    cudaGetSymbolAddress((void**)&wembf,g_wemb_f);

    cudaFuncSetAttribute((const void*)mma_gemm<0,128,128,2>, cudaFuncAttributeMaxDynamicSharedMemorySize, SMEMB(128,128));
    cudaFuncSetAttribute((const void*)mma_gemm<1,64,128,2>,  cudaFuncAttributeMaxDynamicSharedMemorySize, SMEMB(64,128));
    cudaFuncSetAttribute((const void*)mma_gemm<2,64,128,2>,  cudaFuncAttributeMaxDynamicSharedMemorySize, SMEMB(64,128));
    cudaFuncSetAttribute((const void*)mma_gemm<3,64,128,2>,  cudaFuncAttributeMaxDynamicSharedMemorySize, SMEMB(64,128));

    // launch 0: all weight conversions
    {
        int n0 = NLAYER*2*DINNER*DMODEL/4;
        int n1 = NLAYER*DMODEL*DINNER/4;
        int n2 = NLAYER*XDBL_W*DINNER/4;
        int n3 = NLAYER*DINNER*DTRANK/4;
        int n4 = VOCAB*DMODEL/4;
        int tot = n0 + n1 + n2 + n3 + n4;
        cvt_all_k<<<(tot+255)/256, 256>>>(in_proj_w, winf, n0,
                                          out_proj_w, woutf, n1,
                                          x_proj_w,  wxpf,  n2,
                                          dt_w,      wdtf,  n3,
                                          embed,     wembf, n4);
    }

    embed_k<<<TTOK, 256>>>(tokens, embed, h);

    for (int L = 0; L < NLAYER; L++) {
        rmsnorm_k<<<TTOK, 256>>>(h, norm_w + (size_t)L * DMODEL, xnf);

        // in_proj: [2048,1024] x [4096,1024]^T -> xz  (launch 3 at L=0: ncu slot)
        mma_gemm<0,128,128,2><<<dim3(2*DINNER/128, TTOK/128), 256, SMEMB(128,128)>>>(
            xnf, DMODEL, winf + (size_t)L * 2*DINNER*DMODEL, DMODEL,
            xz, 2*DINNER, nullptr, nullptr, 2*DINNER, DMODEL);

        conv_silu_k<<<(TTOK*DINNER + 255)/256, 256>>>(
            xz, conv_w + (size_t)L * DINNER*DCONV, conv_b + (size_t)L * DINNER,
            xc, xcf);

        // x_proj: [2048,2048] x [96,2048]^T -> xdbl (fp32 + fp16 aux)
        mma_gemm<3,64,128,2><<<dim3(1, TTOK/64), 256, SMEMB(64,128)>>>(
            xcf, DINNER, wxpf + (size_t)L * XDBL_W*DINNER, DINNER,
            xdbl, XDBL_W, nullptr, xdf, XDBL_W, DINNER);

        // dt: softplus([2048,96(:64)] x [2048,64]^T + dt_b)
        mma_gemm<2,64,128,2><<<dim3(DINNER/128, TTOK/64), 256, SMEMB(64,128)>>>(
            xdf, XDBL_W, wdtf + (size_t)L * DINNER*DTRANK, DTRANK,
            dts, DINNER, dt_b + (size_t)L * DINNER, nullptr, DINNER, DTRANK);

        scan_k<<<256, 256>>>(xdbl, dts, xc, xz,
                             A_log + (size_t)L * DINNER*DSTATE,
                             D_skip + (size_t)L * DINNER, yf);

        // out_proj (+residual): [2048,2048] x [1024,2048]^T += h
        mma_gemm<1,64,128,2><<<dim3(DMODEL/128, TTOK/64), 256, SMEMB(64,128)>>>(
            yf, DINNER, woutf + (size_t)L * DMODEL*DINNER, DINNER,
            h, DMODEL, nullptr, nullptr, DMODEL, DINNER);
    }

    rmsnorm_k<<<TTOK, 256>>>(h, final_norm_w, xnf);

    // logits: [2048,1024] x [32000,1024]^T
    mma_gemm<0,128,128,2><<<dim3(VOCAB/128, TTOK/128), 256, SMEMB(128,128)>>>(
        xnf, DMODEL, wembf, DMODEL, out, VOCAB, nullptr, nullptr, VOCAB, DMODEL);
}

// round 10
// speedup vs baseline: 1.8059x; 1.1399x over previous
#include <cuda_runtime.h>
#include <cuda_fp16.h>
#include <math.h>
#include <stdint.h>

#define BATCH   2
#define SEQ     1024
#define DMODEL  1024
#define NLAYER  4
#define VOCAB   32000
#define DSTATE  16
#define DCONV   4
#define DINNER  2048
#define DTRANK  64
#define TTOK    (BATCH*SEQ)
#define XDBL_W  96
#define XP_SPLIT 8

// -------- fp32 scratch --------
__device__ float g_h   [TTOK*DMODEL];
__device__ float g_xz  [TTOK*2*DINNER];
__device__ float g_xc  [TTOK*DINNER];
__device__ float g_xdbl[TTOK*XDBL_W];
__device__ float g_dt  [TTOK*DINNER];
__device__ float g_xpp [XP_SPLIT*TTOK*XDBL_W];   // x_proj split-K partials
// -------- fp16 activations --------
__device__ __half g_xn_f[TTOK*DMODEL];
__device__ __half g_xc_f[TTOK*DINNER];
__device__ __half g_xd_f[TTOK*XDBL_W];
__device__ __half g_y_f [TTOK*DINNER];
// -------- fp16 weights --------
__device__ __half g_win_f [NLAYER*2*DINNER*DMODEL];
__device__ __half g_wout_f[NLAYER*DMODEL*DINNER];
__device__ __half g_wxp_f [NLAYER*XDBL_W*DINNER];
__device__ __half g_wdt_f [NLAYER*DINNER*DTRANK];
__device__ __half g_wemb_f[VOCAB*DMODEL];

// ---------------- helpers ----------------
__device__ __forceinline__ void cp16(uint32_t dst, const void* src, int srcBytes) {
    asm volatile("cp.async.cg.shared.global [%0], [%1], 16, %2;"
                 :: "r"(dst), "l"(src), "r"(srcBytes));
}
__device__ __forceinline__ void cp_commit() { asm volatile("cp.async.commit_group;"); }
template<int N> __device__ __forceinline__ void cp_wait() {
    asm volatile("cp.async.wait_group %0;" :: "n"(N));
}
__device__ __forceinline__ void ldsm4(uint32_t* r, uint32_t addr) {
    asm volatile("ldmatrix.sync.aligned.m8n8.x4.shared.b16 {%0,%1,%2,%3}, [%4];"
                 : "=r"(r[0]), "=r"(r[1]), "=r"(r[2]), "=r"(r[3]) : "r"(addr));
}
__device__ __forceinline__ void mma16(float* d, const uint32_t* a, uint32_t b0, uint32_t b1) {
    asm volatile(
        "mma.sync.aligned.m16n8k16.row.col.f32.f16.f16.f32 "
        "{%0,%1,%2,%3}, {%4,%5,%6,%7}, {%8,%9}, {%0,%1,%2,%3};\n"
        : "+f"(d[0]), "+f"(d[1]), "+f"(d[2]), "+f"(d[3])
        : "r"(a[0]), "r"(a[1]), "r"(a[2]), "r"(a[3]), "r"(b0), "r"(b1));
}
__device__ __forceinline__ uint32_t pack2h(float a, float b) {
    __half2 p = __floats2half2_rn(a, b);
    return *(uint32_t*)&p;
}

// ---------------- elementwise kernels ----------------
__global__ void cvt_all_k(const float* __restrict__ s0, __half* __restrict__ d0, int n0,
                          const float* __restrict__ s1, __half* __restrict__ d1, int n1,
                          const float* __restrict__ s2, __half* __restrict__ d2, int n2,
                          const float* __restrict__ s3, __half* __restrict__ d3, int n3,
                          const float* __restrict__ s4, __half* __restrict__ d4, int n4)
{
    int i = blockIdx.x * blockDim.x + threadIdx.x;
    const float* s; __half* d; int j = i;
    if (i < n0)                       { s = s0; d = d0; }
    else if ((j -= n0) < n1)          { s = s1; d = d1; }
    else if ((j -= n1) < n2)          { s = s2; d = d2; }
    else if ((j -= n2) < n3)          { s = s3; d = d3; }
    else if ((j -= n3) < n4)          { s = s4; d = d4; }
    else return;
    float4 v = ((const float4*)s)[j];
    uint2 p;
    p.x = pack2h(v.x, v.y);
    p.y = pack2h(v.z, v.w);
    ((uint2*)d)[j] = p;
}

__global__ void embed_k(const int* __restrict__ tok, const float* __restrict__ emb,
                        float* __restrict__ out)
{
    int t = blockIdx.x;
    int row = tok[t];
    ((float4*)(out + (size_t)t * DMODEL))[threadIdx.x] =
        ((const float4*)(emb + (size_t)row * DMODEL))[threadIdx.x];
}

__global__ void rmsnorm_k(const float* __restrict__ x, const float* __restrict__ w,
                          __half* __restrict__ oh)
{
    int t = blockIdx.x;
    int tid = threadIdx.x;
    float4 v = ((const float4*)(x + (size_t)t * DMODEL))[tid];
    float ss = v.x*v.x + v.y*v.y + v.z*v.z + v.w*v.w;
    __shared__ float sbuf[8];
    #pragma unroll
    for (int o = 16; o; o >>= 1) ss += __shfl_xor_sync(0xffffffffu, ss, o);
    int warp = tid >> 5, lane = tid & 31;
    if (lane == 0) sbuf[warp] = ss;
    __syncthreads();
    if (warp == 0) {
        float s2 = (lane < 8) ? sbuf[lane] : 0.f;
        #pragma unroll
        for (int o = 4; o; o >>= 1) s2 += __shfl_xor_sync(0xffffffffu, s2, o);
        if (lane == 0) sbuf[0] = rsqrtf(s2 * (1.0f / DMODEL) + 1e-5f);
    }
    __syncthreads();
    float r = sbuf[0];
    float4 wv = ((const float4*)w)[tid];
    uint2 p;
    p.x = pack2h(v.x*r*wv.x, v.y*r*wv.y);
    p.y = pack2h(v.z*r*wv.z, v.w*r*wv.w);
    ((uint2*)(oh + (size_t)t * DMODEL))[tid] = p;
}

__global__ void conv_silu_k(const float* __restrict__ xz, const float* __restrict__ cw,
                            const float* __restrict__ cb, float* __restrict__ xc,
                            __half* __restrict__ xch)
{
    int idx = blockIdx.x * blockDim.x + threadIdx.x;
    if (idx >= TTOK * DINNER) return;
    int c = idx % DINNER;
    int t = idx / DINNER;
    int l = t % SEQ;
    float4 w4 = *(const float4*)(cw + c * 4);
    const size_t str = 2 * DINNER;
    float acc = cb[c];
    if (l >= 3) acc += w4.x * xz[(size_t)(t-3)*str + c];
    if (l >= 2) acc += w4.y * xz[(size_t)(t-2)*str + c];
    if (l >= 1) acc += w4.z * xz[(size_t)(t-1)*str + c];
    acc += w4.w * xz[(size_t)t*str + c];
    float s = 1.f / (1.f + expf(-acc));
    float o = acc * s;
    xc[idx] = o;
    xch[idx] = __float2half_rn(o);
}

// x_proj split-K reduce: sum 8 partials, emit fp32 + fp16
__global__ void reduce_xp_k(const float* __restrict__ parts,
                            float* __restrict__ xdbl, __half* __restrict__ xdf)
{
    int i = blockIdx.x * blockDim.x + threadIdx.x;
    if (i >= TTOK * XDBL_W) return;
    float s = 0.f;
    #pragma unroll
    for (int p = 0; p < XP_SPLIT; p++)
        s += parts[(size_t)p * TTOK * XDBL_W + i];
    xdbl[i] = s;
    xdf[i] = __float2half_rn(s);
}

// selective scan: PF-deep register pipeline; dA/w precomputed off the chain.
#define PF 8
__global__ __launch_bounds__(256)
void scan_k(const float* __restrict__ xdbl, const float* __restrict__ dt,
            const float* __restrict__ xc,   const float* __restrict__ xz,
            const float* __restrict__ A_log, const float* __restrict__ Dsk,
            __half* __restrict__ yh)
{
    int s = threadIdx.x & 15;
    int c = ((blockIdx.x & 127) << 4) + (threadIdx.x >> 4);
    int b = blockIdx.x >> 7;
    float A = -expf(A_log[(size_t)c * DSTATE + s]);
    float dval = Dsk[c];
    bool lane0 = (s == 0);
    float h = 0.f;
    int tbase = b * SEQ;

    float pdA[PF], pw[PF], pC[PF], pxv[PF];
    #pragma unroll
    for (int j = 0; j < PF; j++) {
        int t = tbase + j;
        float dtv = dt[(size_t)t * DINNER + c];
        float xv  = xc[(size_t)t * DINNER + c];
        float Bv  = xdbl[(size_t)t * XDBL_W + DTRANK + s];
        pC[j]  = xdbl[(size_t)t * XDBL_W + DTRANK + DSTATE + s];
        pdA[j] = __expf(dtv * A);
        pw[j]  = dtv * xv * Bv;
        pxv[j] = xv;
    }

    for (int l0 = 0; l0 < SEQ; l0 += PF) {
        #pragma unroll
        for (int j = 0; j < PF; j++) {
            int t = tbase + l0 + j;
            float dA = pdA[j], w = pw[j], Cv = pC[j], xv = pxv[j];

            // prefetch step l0+PF+j into slot j (independent of recurrence)
            int tn = (l0 + PF + j < SEQ) ? t + PF : t;
            float dtv = dt[(size_t)tn * DINNER + c];
            float x2  = xc[(size_t)tn * DINNER + c];
            float B2  = xdbl[(size_t)tn * XDBL_W + DTRANK + s];
            pC[j]  = xdbl[(size_t)tn * XDBL_W + DTRANK + DSTATE + s];
            pdA[j] = __expf(dtv * A);
            pw[j]  = dtv * x2 * B2;
            pxv[j] = x2;

            // critical path: one FFMA
            h = dA * h + w;
            float p = h * Cv;
            p += __shfl_xor_sync(0xffffffffu, p, 8);
            p += __shfl_xor_sync(0xffffffffu, p, 4);
            p += __shfl_xor_sync(0xffffffffu, p, 2);
            p += __shfl_xor_sync(0xffffffffu, p, 1);
            if (lane0) {
                float z = xz[(size_t)t * (2*DINNER) + DINNER + c];
                float sg = 1.f / (1.f + __expf(-z));
                yh[(size_t)t * DINNER + c] = __float2half_rn((p + dval * xv) * (z * sg));
            }
        }
    }
}

// ----------------------------------------------------------
// FP16 HMMA GEMM (NT): C[T,N] = A[T,K] x W[N,K]^T
// CTA BMxBN, 8 warps, warp tile 64 x (BN/(8/(BM/64))), KCH=64, rows 144B.
// 3-stage cp.async, ONE barrier per chunk. blockIdx.z = K-split part:
// A,W advance z*K elements; C advances z*zstride.
// EPI: 0=store 1=accum 2=softplus+bias
// ----------------------------------------------------------
#define KCH     64
#define ROWB    144

template<int EPI, int BM, int BN, int MB>
__global__ __launch_bounds__(256, MB)
void mma_gemm(const __half* __restrict__ A, int lda,
              const __half* __restrict__ W, int ldw,
              float* __restrict__ C, int ldc,
              const float* __restrict__ bias,
              int N, int K, int zstride)
{
    constexpr int WM    = BM / 64;
    constexpr int WNW   = 8 / WM;
    constexpr int WN    = BN / WNW;
    constexpr int NFR   = WN / 8;
    constexpr int NBL   = WN / 16;
    constexpr int TILEA = BM * ROWB;
    constexpr int TILEB = BN * ROWB;
    constexpr int STAGE = TILEA + TILEB;
    constexpr int NTASK = (BM + BN) * 8;

    extern __shared__ char smem[];
    uint32_t sb = (uint32_t)__cvta_generic_to_shared(smem);

    int tid = threadIdx.x, lane = tid & 31, warp = tid >> 5;
    int wm = warp % WM;
    int wn = warp / WM;
    int tileM = blockIdx.y * BM, tileN = blockIdx.x * BN;

    // K-split offsets
    int z = blockIdx.z;
    A += (size_t)z * K;
    W += (size_t)z * K;
    C += (size_t)z * zstride;

    float acc[4][NFR][4];
    #pragma unroll
    for (int mi = 0; mi < 4; mi++)
        #pragma unroll
        for (int ni = 0; ni < NFR; ni++)
            #pragma unroll
            for (int e = 0; e < 4; e++) acc[mi][ni][e] = 0.f;

    const int iters = K / KCH;

    uint32_t laneAoff = (uint32_t)((wm*64 + (lane & 15)) * ROWB + ((lane >> 4) & 1) * 16);
    uint32_t laneBoff = (uint32_t)((wn*WN + (lane & 7) + ((lane >= 16) ? 8 : 0)) * ROWB
                                   + ((lane >> 3) & 1) * 16);

    auto load_chunk = [&](int s, int it) {
        int k0 = it * KCH;
        uint32_t sbase = sb + (uint32_t)(s * STAGE);
        #pragma unroll
        for (int i = 0; i < NTASK/256; i++) {
            int task = tid + i * 256;
            if (task < BM*8) {
                int r = task >> 3, c = task & 7;
                cp16(sbase + (uint32_t)(r * ROWB + c * 16),
                     A + (size_t)(tileM + r) * lda + k0 + c * 8, 16);
            } else {
                int t2 = task - BM*8;
                int r = t2 >> 3, c = t2 & 7;
                int wr = tileN + r;
                const __half* src = W + (size_t)(wr < N ? wr : 0) * ldw + k0 + c * 8;
                cp16(sbase + (uint32_t)(TILEA + r * ROWB + c * 16),
                     src, wr < N ? 16 : 0);
            }
        }
        cp_commit();
    };

    if (iters > 0) load_chunk(0, 0);
    if (iters > 1) load_chunk(1, 1);

    for (int it = 0; it < iters; it++) {
        if (iters - 1 - it >= 1) cp_wait<1>();
        else                     cp_wait<0>();
        __syncthreads();                         // single barrier per chunk
        if (it + 2 < iters) load_chunk((it + 2) % 3, it + 2);

        int s = it % 3;
        uint32_t stA = sb + s*STAGE + laneAoff;
        uint32_t stB = sb + s*STAGE + TILEA + laneBoff;

        #pragma unroll
        for (int ks = 0; ks < 4; ks++) {
            uint32_t a[4][4], b[NBL][4];
            #pragma unroll
            for (int mi = 0; mi < 4; mi++)
                ldsm4(a[mi], stA + mi*16*ROWB + ks*32);
            #pragma unroll
            for (int pi = 0; pi < NBL; pi++)
                ldsm4(b[pi], stB + pi*16*ROWB + ks*32);
            #pragma unroll
            for (int mi = 0; mi < 4; mi++)
                #pragma unroll
                for (int ni = 0; ni < NFR; ni++) {
                    int pi = ni >> 1, j = (ni & 1) * 2;
                    mma16(acc[mi][ni], a[mi], b[pi][j], b[pi][j+1]);
                }
        }
    }

    // ---- epilogue ----
    int g = lane >> 2, t4 = lane & 3;
    int warpN0 = tileN + wn*WN;
    #pragma unroll
    for (int mi = 0; mi < 4; mi++) {
        int r0 = tileM + wm*64 + mi*16 + g;
        #pragma unroll
        for (int ni = 0; ni < NFR; ni++) {
            int c = warpN0 + ni*8 + 2*t4;
            if (c >= N) continue;
            float2 v0 = make_float2(acc[mi][ni][0], acc[mi][ni][1]);
            float2 v1 = make_float2(acc[mi][ni][2], acc[mi][ni][3]);
            float* p0 = C + (size_t)r0 * ldc + c;
            float* p1 = C + (size_t)(r0 + 8) * ldc + c;
            if (EPI == 1) {
                float2 o0 = *(float2*)p0, o1 = *(float2*)p1;
                v0.x += o0.x; v0.y += o0.y; v1.x += o1.x; v1.y += o1.y;
            } else if (EPI == 2) {
                float b0 = bias[c], b1 = bias[c+1];
                v0.x += b0; v0.y += b1; v1.x += b0; v1.y += b1;
                v0.x = (v0.x > 20.f) ? v0.x : log1pf(expf(v0.x));
                v0.y = (v0.y > 20.f) ? v0.y : log1pf(expf(v0.y));
                v1.x = (v1.x > 20.f) ? v1.x : log1pf(expf(v1.x));
                v1.y = (v1.y > 20.f) ? v1.y : log1pf(expf(v1.y));
            }
            *(float2*)p0 = v0;
            *(float2*)p1 = v1;
        }
    }
}

#define SMEMB(BM,BN) (3 * ((BM) + (BN)) * ROWB)

// ----------------------------------------------------------
extern "C" void kernel_launch(void* const* d_in, const int* in_sizes, int n_in,
                              void* d_out, int out_size)
{
    const int*   tokens       = (const int*)  d_in[0];
    const float* embed        = (const float*)d_in[1];
    const float* norm_w       = (const float*)d_in[2];
    const float* in_proj_w    = (const float*)d_in[3];
    const float* conv_w       = (const float*)d_in[4];
    const float* conv_b       = (const float*)d_in[5];
    const float* x_proj_w     = (const float*)d_in[6];
    const float* dt_w         = (const float*)d_in[7];
    const float* dt_b         = (const float*)d_in[8];
    const float* A_log        = (const float*)d_in[9];
    const float* D_skip       = (const float*)d_in[10];
    const float* out_proj_w   = (const float*)d_in[11];
    const float* final_norm_w = (const float*)d_in[12];
    float* out = (float*)d_out;

    float *h, *xz, *xc, *xdbl, *dts, *xpp;
    __half *xnf,*xcf,*xdf,*yf;
    __half *winf,*woutf,*wxpf,*wdtf,*wembf;
    cudaGetSymbolAddress((void**)&h,    g_h);
    cudaGetSymbolAddress((void**)&xz,   g_xz);
    cudaGetSymbolAddress((void**)&xc,   g_xc);
    cudaGetSymbolAddress((void**)&xdbl, g_xdbl);
    cudaGetSymbolAddress((void**)&dts,  g_dt);
    cudaGetSymbolAddress((void**)&xpp,  g_xpp);
    cudaGetSymbolAddress((void**)&xnf,  g_xn_f);
    cudaGetSymbolAddress((void**)&xcf,  g_xc_f);
    cudaGetSymbolAddress((void**)&xdf,  g_xd_f);
    cudaGetSymbolAddress((void**)&yf,   g_y_f);
    cudaGetSymbolAddress((void**)&winf, g_win_f);
    cudaGetSymbolAddress((void**)&woutf,g_wout_f);
    cudaGetSymbolAddress((void**)&wxpf, g_wxp_f);
    cudaGetSymbolAddress((void**)&wdtf, g_wdt_f);
    cudaGetSymbolAddress((void**)&wembf,g_wemb_f);

    cudaFuncSetAttribute((const void*)mma_gemm<0,128,128,2>, cudaFuncAttributeMaxDynamicSharedMemorySize, SMEMB(128,128));
    cudaFuncSetAttribute((const void*)mma_gemm<0,64,128,2>,  cudaFuncAttributeMaxDynamicSharedMemorySize, SMEMB(64,128));
    cudaFuncSetAttribute((const void*)mma_gemm<1,64,128,2>,  cudaFuncAttributeMaxDynamicSharedMemorySize, SMEMB(64,128));
    cudaFuncSetAttribute((const void*)mma_gemm<2,64,128,2>,  cudaFuncAttributeMaxDynamicSharedMemorySize, SMEMB(64,128));

    // launch 0: all weight conversions
    {
        int n0 = NLAYER*2*DINNER*DMODEL/4;
        int n1 = NLAYER*DMODEL*DINNER/4;
        int n2 = NLAYER*XDBL_W*DINNER/4;
        int n3 = NLAYER*DINNER*DTRANK/4;
        int n4 = VOCAB*DMODEL/4;
        int tot = n0 + n1 + n2 + n3 + n4;
        cvt_all_k<<<(tot+255)/256, 256>>>(in_proj_w, winf, n0,
                                          out_proj_w, woutf, n1,
                                          x_proj_w,  wxpf,  n2,
                                          dt_w,      wdtf,  n3,
                                          embed,     wembf, n4);
    }

    embed_k<<<TTOK, 256>>>(tokens, embed, h);

    for (int L = 0; L < NLAYER; L++) {
        rmsnorm_k<<<TTOK, 256>>>(h, norm_w + (size_t)L * DMODEL, xnf);

        // in_proj: [2048,1024] x [4096,1024]^T -> xz
        mma_gemm<0,128,128,2><<<dim3(2*DINNER/128, TTOK/128), 256, SMEMB(128,128)>>>(
            xnf, DMODEL, winf + (size_t)L * 2*DINNER*DMODEL, DMODEL,
            xz, 2*DINNER, nullptr, 2*DINNER, DMODEL, 0);

        conv_silu_k<<<(TTOK*DINNER + 255)/256, 256>>>(
            xz, conv_w + (size_t)L * DINNER*DCONV, conv_b + (size_t)L * DINNER,
            xc, xcf);

        // x_proj split-K=8: each z computes K=256 slice -> partials
        mma_gemm<0,64,128,2><<<dim3(1, TTOK/64, XP_SPLIT), 256, SMEMB(64,128)>>>(
            xcf, DINNER, wxpf + (size_t)L * XDBL_W*DINNER, DINNER,
            xpp, XDBL_W, nullptr, XDBL_W, DINNER/XP_SPLIT, TTOK*XDBL_W);

        reduce_xp_k<<<(TTOK*XDBL_W + 255)/256, 256>>>(xpp, xdbl, xdf);

        // dt: softplus([2048,96(:64)] x [2048,64]^T + dt_b)
        mma_gemm<2,64,128,2><<<dim3(DINNER/128, TTOK/64), 256, SMEMB(64,128)>>>(
            xdf, XDBL_W, wdtf + (size_t)L * DINNER*DTRANK, DTRANK,
            dts, DINNER, dt_b + (size_t)L * DINNER, DINNER, DTRANK, 0);

        scan_k<<<256, 256>>>(xdbl, dts, xc, xz,
                             A_log + (size_t)L * DINNER*DSTATE,
                             D_skip + (size_t)L * DINNER, yf);

        // out_proj (+residual): [2048,2048] x [1024,2048]^T += h
        mma_gemm<1,64,128,2><<<dim3(DMODEL/128, TTOK/64), 256, SMEMB(64,128)>>>(
            yf, DINNER, woutf + (size_t)L * DMODEL*DINNER, DINNER,
            h, DMODEL, nullptr, DMODEL, DINNER, 0);
    }

    rmsnorm_k<<<TTOK, 256>>>(h, final_norm_w, xnf);

    // logits: [2048,1024] x [32000,1024]^T
    mma_gemm<0,128,128,2><<<dim3(VOCAB/128, TTOK/128), 256, SMEMB(128,128)>>>(
        xnf, DMODEL, wembf, DMODEL, out, VOCAB, nullptr, VOCAB, DMODEL, 0);
}

// round 11
// speedup vs baseline: 1.8340x; 1.0155x over previous
#include <cuda_runtime.h>
#include <cuda_fp16.h>
#include <math.h>
#include <stdint.h>

#define BATCH   2
#define SEQ     1024
#define DMODEL  1024
#define NLAYER  4
#define VOCAB   32000
#define DSTATE  16
#define DCONV   4
#define DINNER  2048
#define DTRANK  64
#define TTOK    (BATCH*SEQ)
#define XDBL_W  96
#define XP_SPLIT 8
#define OP_SPLIT 2

// -------- fp32 scratch --------
__device__ float g_h   [TTOK*DMODEL];
__device__ float g_xz  [TTOK*2*DINNER];
__device__ float g_xc  [TTOK*DINNER];
__device__ float g_xdbl[TTOK*XDBL_W];
__device__ float g_dt  [TTOK*DINNER];
__device__ float g_xpp [XP_SPLIT*TTOK*XDBL_W];   // x_proj split-K partials
__device__ float g_opp [OP_SPLIT*TTOK*DMODEL];   // out_proj split-K partials
// -------- fp16 activations --------
__device__ __half g_xn_f[TTOK*DMODEL];
__device__ __half g_xc_f[TTOK*DINNER];
__device__ __half g_xd_f[TTOK*XDBL_W];
__device__ __half g_y_f [TTOK*DINNER];
// -------- fp16 weights --------
__device__ __half g_win_f [NLAYER*2*DINNER*DMODEL];
__device__ __half g_wout_f[NLAYER*DMODEL*DINNER];
__device__ __half g_wxp_f [NLAYER*XDBL_W*DINNER];
__device__ __half g_wdt_f [NLAYER*DINNER*DTRANK];
__device__ __half g_wemb_f[VOCAB*DMODEL];

// ---------------- helpers ----------------
__device__ __forceinline__ void cp16(uint32_t dst, const void* src, int srcBytes) {
    asm volatile("cp.async.cg.shared.global [%0], [%1], 16, %2;"
                 :: "r"(dst), "l"(src), "r"(srcBytes));
}
__device__ __forceinline__ void cp_commit() { asm volatile("cp.async.commit_group;"); }
template<int N> __device__ __forceinline__ void cp_wait() {
    asm volatile("cp.async.wait_group %0;" :: "n"(N));
}
__device__ __forceinline__ void ldsm4(uint32_t* r, uint32_t addr) {
    asm volatile("ldmatrix.sync.aligned.m8n8.x4.shared.b16 {%0,%1,%2,%3}, [%4];"
                 : "=r"(r[0]), "=r"(r[1]), "=r"(r[2]), "=r"(r[3]) : "r"(addr));
}
__device__ __forceinline__ void mma16(float* d, const uint32_t* a, uint32_t b0, uint32_t b1) {
    asm volatile(
        "mma.sync.aligned.m16n8k16.row.col.f32.f16.f16.f32 "
        "{%0,%1,%2,%3}, {%4,%5,%6,%7}, {%8,%9}, {%0,%1,%2,%3};\n"
        : "+f"(d[0]), "+f"(d[1]), "+f"(d[2]), "+f"(d[3])
        : "r"(a[0]), "r"(a[1]), "r"(a[2]), "r"(a[3]), "r"(b0), "r"(b1));
}
__device__ __forceinline__ uint32_t pack2h(float a, float b) {
    __half2 p = __floats2half2_rn(a, b);
    return *(uint32_t*)&p;
}

// ---------------- elementwise kernels ----------------
__global__ void cvt_all_k(const float* __restrict__ s0, __half* __restrict__ d0, int n0,
                          const float* __restrict__ s1, __half* __restrict__ d1, int n1,
                          const float* __restrict__ s2, __half* __restrict__ d2, int n2,
                          const float* __restrict__ s3, __half* __restrict__ d3, int n3,
                          const float* __restrict__ s4, __half* __restrict__ d4, int n4)
{
    int i = blockIdx.x * blockDim.x + threadIdx.x;
    const float* s; __half* d; int j = i;
    if (i < n0)                       { s = s0; d = d0; }
    else if ((j -= n0) < n1)          { s = s1; d = d1; }
    else if ((j -= n1) < n2)          { s = s2; d = d2; }
    else if ((j -= n2) < n3)          { s = s3; d = d3; }
    else if ((j -= n3) < n4)          { s = s4; d = d4; }
    else return;
    float4 v = ((const float4*)s)[j];
    uint2 p;
    p.x = pack2h(v.x, v.y);
    p.y = pack2h(v.z, v.w);
    ((uint2*)d)[j] = p;
}

__global__ void embed_k(const int* __restrict__ tok, const float* __restrict__ emb,
                        float* __restrict__ out)
{
    int t = blockIdx.x;
    int row = tok[t];
    ((float4*)(out + (size_t)t * DMODEL))[threadIdx.x] =
        ((const float4*)(emb + (size_t)row * DMODEL))[threadIdx.x];
}

__global__ void rmsnorm_k(const float* __restrict__ x, const float* __restrict__ w,
                          __half* __restrict__ oh)
{
    int t = blockIdx.x;
    int tid = threadIdx.x;
    float4 v = ((const float4*)(x + (size_t)t * DMODEL))[tid];
    float ss = v.x*v.x + v.y*v.y + v.z*v.z + v.w*v.w;
    __shared__ float sbuf[8];
    #pragma unroll
    for (int o = 16; o; o >>= 1) ss += __shfl_xor_sync(0xffffffffu, ss, o);
    int warp = tid >> 5, lane = tid & 31;
    if (lane == 0) sbuf[warp] = ss;
    __syncthreads();
    if (warp == 0) {
        float s2 = (lane < 8) ? sbuf[lane] : 0.f;
        #pragma unroll
        for (int o = 4; o; o >>= 1) s2 += __shfl_xor_sync(0xffffffffu, s2, o);
        if (lane == 0) sbuf[0] = rsqrtf(s2 * (1.0f / DMODEL) + 1e-5f);
    }
    __syncthreads();
    float r = sbuf[0];
    float4 wv = ((const float4*)w)[tid];
    uint2 p;
    p.x = pack2h(v.x*r*wv.x, v.y*r*wv.y);
    p.y = pack2h(v.z*r*wv.z, v.w*r*wv.w);
    ((uint2*)(oh + (size_t)t * DMODEL))[tid] = p;
}

__global__ void conv_silu_k(const float* __restrict__ xz, const float* __restrict__ cw,
                            const float* __restrict__ cb, float* __restrict__ xc,
                            __half* __restrict__ xch)
{
    int idx = blockIdx.x * blockDim.x + threadIdx.x;
    if (idx >= TTOK * DINNER) return;
    int c = idx % DINNER;
    int t = idx / DINNER;
    int l = t % SEQ;
    float4 w4 = *(const float4*)(cw + c * 4);
    const size_t str = 2 * DINNER;
    float acc = cb[c];
    if (l >= 3) acc += w4.x * xz[(size_t)(t-3)*str + c];
    if (l >= 2) acc += w4.y * xz[(size_t)(t-2)*str + c];
    if (l >= 1) acc += w4.z * xz[(size_t)(t-1)*str + c];
    acc += w4.w * xz[(size_t)t*str + c];
    float s = 1.f / (1.f + expf(-acc));
    float o = acc * s;
    xc[idx] = o;
    xch[idx] = __float2half_rn(o);
}

// x_proj split-K reduce: sum 8 partials, emit fp32 + fp16
__global__ void reduce_xp_k(const float* __restrict__ parts,
                            float* __restrict__ xdbl, __half* __restrict__ xdf)
{
    int i = blockIdx.x * blockDim.x + threadIdx.x;
    if (i >= TTOK * XDBL_W) return;
    float s = 0.f;
    #pragma unroll
    for (int p = 0; p < XP_SPLIT; p++)
        s += parts[(size_t)p * TTOK * XDBL_W + i];
    xdbl[i] = s;
    xdf[i] = __float2half_rn(s);
}

// out_proj split-K reduce: h += p0 + p1 (vectorized)
__global__ void reduce_op_k(const float* __restrict__ parts, float* __restrict__ h)
{
    int i = blockIdx.x * blockDim.x + threadIdx.x;
    if (i >= TTOK * DMODEL / 4) return;
    float4 a = ((const float4*)parts)[i];
    float4 b = ((const float4*)(parts + (size_t)TTOK * DMODEL))[i];
    float4 o = ((float4*)h)[i];
    o.x += a.x + b.x; o.y += a.y + b.y;
    o.z += a.z + b.z; o.w += a.w + b.w;
    ((float4*)h)[i] = o;
}

// selective scan: PF-deep register pipeline; dA/w precomputed off the chain.
#define PF 8
__global__ __launch_bounds__(256)
void scan_k(const float* __restrict__ xdbl, const float* __restrict__ dt,
            const float* __restrict__ xc,   const float* __restrict__ xz,
            const float* __restrict__ A_log, const float* __restrict__ Dsk,
            __half* __restrict__ yh)
{
    int s = threadIdx.x & 15;
    int c = ((blockIdx.x & 127) << 4) + (threadIdx.x >> 4);
    int b = blockIdx.x >> 7;
    float A = -expf(A_log[(size_t)c * DSTATE + s]);
    float dval = Dsk[c];
    bool lane0 = (s == 0);
    float h = 0.f;
    int tbase = b * SEQ;

    float pdA[PF], pw[PF], pC[PF], pxv[PF];
    #pragma unroll
    for (int j = 0; j < PF; j++) {
        int t = tbase + j;
        float dtv = dt[(size_t)t * DINNER + c];
        float xv  = xc[(size_t)t * DINNER + c];
        float Bv  = xdbl[(size_t)t * XDBL_W + DTRANK + s];
        pC[j]  = xdbl[(size_t)t * XDBL_W + DTRANK + DSTATE + s];
        pdA[j] = __expf(dtv * A);
        pw[j]  = dtv * xv * Bv;
        pxv[j] = xv;
    }

    for (int l0 = 0; l0 < SEQ; l0 += PF) {
        #pragma unroll
        for (int j = 0; j < PF; j++) {
            int t = tbase + l0 + j;
            float dA = pdA[j], w = pw[j], Cv = pC[j], xv = pxv[j];

            int tn = (l0 + PF + j < SEQ) ? t + PF : t;
            float dtv = dt[(size_t)tn * DINNER + c];
            float x2  = xc[(size_t)tn * DINNER + c];
            float B2  = xdbl[(size_t)tn * XDBL_W + DTRANK + s];
            pC[j]  = xdbl[(size_t)tn * XDBL_W + DTRANK + DSTATE + s];
            pdA[j] = __expf(dtv * A);
            pw[j]  = dtv * x2 * B2;
            pxv[j] = x2;

            h = dA * h + w;
            float p = h * Cv;
            p += __shfl_xor_sync(0xffffffffu, p, 8);
            p += __shfl_xor_sync(0xffffffffu, p, 4);
            p += __shfl_xor_sync(0xffffffffu, p, 2);
            p += __shfl_xor_sync(0xffffffffu, p, 1);
            if (lane0) {
                float z = xz[(size_t)t * (2*DINNER) + DINNER + c];
                float sg = 1.f / (1.f + __expf(-z));
                yh[(size_t)t * DINNER + c] = __float2half_rn((p + dval * xv) * (z * sg));
            }
        }
    }
}

// ----------------------------------------------------------
// FP16 HMMA GEMM (NT): C[T,N] = A[T,K] x W[N,K]^T
// CTA BMxBN, 8 warps, KCH=64, rows 144B, 3-stage cp.async, one barrier/chunk.
// blockIdx.z: A,W advance z*K; C advances z*zstride.
// EPI: 0=store 1=accum 2=softplus+bias
// ----------------------------------------------------------
#define KCH     64
#define ROWB    144

template<int EPI, int BM, int BN, int MB>
__global__ __launch_bounds__(256, MB)
void mma_gemm(const __half* __restrict__ A, int lda,
              const __half* __restrict__ W, int ldw,
              float* __restrict__ C, int ldc,
              const float* __restrict__ bias,
              int N, int K, int zstride)
{
    constexpr int WM    = BM / 64;
    constexpr int WNW   = 8 / WM;
    constexpr int WN    = BN / WNW;
    constexpr int NFR   = WN / 8;
    constexpr int NBL   = WN / 16;
    constexpr int TILEA = BM * ROWB;
    constexpr int TILEB = BN * ROWB;
    constexpr int STAGE = TILEA + TILEB;
    constexpr int NTASK = (BM + BN) * 8;

    extern __shared__ char smem[];
    uint32_t sb = (uint32_t)__cvta_generic_to_shared(smem);

    int tid = threadIdx.x, lane = tid & 31, warp = tid >> 5;
    int wm = warp % WM;
    int wn = warp / WM;
    int tileM = blockIdx.y * BM, tileN = blockIdx.x * BN;

    int z = blockIdx.z;
    A += (size_t)z * K;
    W += (size_t)z * K;
    C += (size_t)z * zstride;

    float acc[4][NFR][4];
    #pragma unroll
    for (int mi = 0; mi < 4; mi++)
        #pragma unroll
        for (int ni = 0; ni < NFR; ni++)
            #pragma unroll
            for (int e = 0; e < 4; e++) acc[mi][ni][e] = 0.f;

    const int iters = K / KCH;

    uint32_t laneAoff = (uint32_t)((wm*64 + (lane & 15)) * ROWB + ((lane >> 4) & 1) * 16);
    uint32_t laneBoff = (uint32_t)((wn*WN + (lane & 7) + ((lane >= 16) ? 8 : 0)) * ROWB
                                   + ((lane >> 3) & 1) * 16);

    auto load_chunk = [&](int s, int it) {
        int k0 = it * KCH;
        uint32_t sbase = sb + (uint32_t)(s * STAGE);
        #pragma unroll
        for (int i = 0; i < NTASK/256; i++) {
            int task = tid + i * 256;
            if (task < BM*8) {
                int r = task >> 3, c = task & 7;
                cp16(sbase + (uint32_t)(r * ROWB + c * 16),
                     A + (size_t)(tileM + r) * lda + k0 + c * 8, 16);
            } else {
                int t2 = task - BM*8;
                int r = t2 >> 3, c = t2 & 7;
                int wr = tileN + r;
                const __half* src = W + (size_t)(wr < N ? wr : 0) * ldw + k0 + c * 8;
                cp16(sbase + (uint32_t)(TILEA + r * ROWB + c * 16),
                     src, wr < N ? 16 : 0);
            }
        }
        cp_commit();
    };

    if (iters > 0) load_chunk(0, 0);
    if (iters > 1) load_chunk(1, 1);

    for (int it = 0; it < iters; it++) {
        if (iters - 1 - it >= 1) cp_wait<1>();
        else                     cp_wait<0>();
        __syncthreads();
        if (it + 2 < iters) load_chunk((it + 2) % 3, it + 2);

        int s = it % 3;
        uint32_t stA = sb + s*STAGE + laneAoff;
        uint32_t stB = sb + s*STAGE + TILEA + laneBoff;

        #pragma unroll
        for (int ks = 0; ks < 4; ks++) {
            uint32_t a[4][4], b[NBL][4];
            #pragma unroll
            for (int mi = 0; mi < 4; mi++)
                ldsm4(a[mi], stA + mi*16*ROWB + ks*32);
            #pragma unroll
            for (int pi = 0; pi < NBL; pi++)
                ldsm4(b[pi], stB + pi*16*ROWB + ks*32);
            #pragma unroll
            for (int mi = 0; mi < 4; mi++)
                #pragma unroll
                for (int ni = 0; ni < NFR; ni++) {
                    int pi = ni >> 1, j = (ni & 1) * 2;
                    mma16(acc[mi][ni], a[mi], b[pi][j], b[pi][j+1]);
                }
        }
    }

    // ---- epilogue ----
    int g = lane >> 2, t4 = lane & 3;
    int warpN0 = tileN + wn*WN;
    #pragma unroll
    for (int mi = 0; mi < 4; mi++) {
        int r0 = tileM + wm*64 + mi*16 + g;
        #pragma unroll
        for (int ni = 0; ni < NFR; ni++) {
            int c = warpN0 + ni*8 + 2*t4;
            if (c >= N) continue;
            float2 v0 = make_float2(acc[mi][ni][0], acc[mi][ni][1]);
            float2 v1 = make_float2(acc[mi][ni][2], acc[mi][ni][3]);
            float* p0 = C + (size_t)r0 * ldc + c;
            float* p1 = C + (size_t)(r0 + 8) * ldc + c;
            if (EPI == 1) {
                float2 o0 = *(float2*)p0, o1 = *(float2*)p1;
                v0.x += o0.x; v0.y += o0.y; v1.x += o1.x; v1.y += o1.y;
            } else if (EPI == 2) {
                float b0 = bias[c], b1 = bias[c+1];
                v0.x += b0; v0.y += b1; v1.x += b0; v1.y += b1;
                v0.x = (v0.x > 20.f) ? v0.x : log1pf(expf(v0.x));
                v0.y = (v0.y > 20.f) ? v0.y : log1pf(expf(v0.y));
                v1.x = (v1.x > 20.f) ? v1.x : log1pf(expf(v1.x));
                v1.y = (v1.y > 20.f) ? v1.y : log1pf(expf(v1.y));
            }
            *(float2*)p0 = v0;
            *(float2*)p1 = v1;
        }
    }
}

#define SMEMB(BM,BN) (3 * ((BM) + (BN)) * ROWB)

// ----------------------------------------------------------
extern "C" void kernel_launch(void* const* d_in, const int* in_sizes, int n_in,
                              void* d_out, int out_size)
{
    const int*   tokens       = (const int*)  d_in[0];
    const float* embed        = (const float*)d_in[1];
    const float* norm_w       = (const float*)d_in[2];
    const float* in_proj_w    = (const float*)d_in[3];
    const float* conv_w       = (const float*)d_in[4];
    const float* conv_b       = (const float*)d_in[5];
    const float* x_proj_w     = (const float*)d_in[6];
    const float* dt_w         = (const float*)d_in[7];
    const float* dt_b         = (const float*)d_in[8];
    const float* A_log        = (const float*)d_in[9];
    const float* D_skip       = (const float*)d_in[10];
    const float* out_proj_w   = (const float*)d_in[11];
    const float* final_norm_w = (const float*)d_in[12];
    float* out = (float*)d_out;

    float *h, *xz, *xc, *xdbl, *dts, *xpp, *opp;
    __half *xnf,*xcf,*xdf,*yf;
    __half *winf,*woutf,*wxpf,*wdtf,*wembf;
    cudaGetSymbolAddress((void**)&h,    g_h);
    cudaGetSymbolAddress((void**)&xz,   g_xz);
    cudaGetSymbolAddress((void**)&xc,   g_xc);
    cudaGetSymbolAddress((void**)&xdbl, g_xdbl);
    cudaGetSymbolAddress((void**)&dts,  g_dt);
    cudaGetSymbolAddress((void**)&xpp,  g_xpp);
    cudaGetSymbolAddress((void**)&opp,  g_opp);
    cudaGetSymbolAddress((void**)&xnf,  g_xn_f);
    cudaGetSymbolAddress((void**)&xcf,  g_xc_f);
    cudaGetSymbolAddress((void**)&xdf,  g_xd_f);
    cudaGetSymbolAddress((void**)&yf,   g_y_f);
    cudaGetSymbolAddress((void**)&winf, g_win_f);
    cudaGetSymbolAddress((void**)&woutf,g_wout_f);
    cudaGetSymbolAddress((void**)&wxpf, g_wxp_f);
    cudaGetSymbolAddress((void**)&wdtf, g_wdt_f);
    cudaGetSymbolAddress((void**)&wembf,g_wemb_f);

    cudaFuncSetAttribute((const void*)mma_gemm<0,128,128,2>, cudaFuncAttributeMaxDynamicSharedMemorySize, SMEMB(128,128));
    cudaFuncSetAttribute((const void*)mma_gemm<2,128,128,2>, cudaFuncAttributeMaxDynamicSharedMemorySize, SMEMB(128,128));

    // launch 0: all weight conversions
    {
        int n0 = NLAYER*2*DINNER*DMODEL/4;
        int n1 = NLAYER*DMODEL*DINNER/4;
        int n2 = NLAYER*XDBL_W*DINNER/4;
        int n3 = NLAYER*DINNER*DTRANK/4;
        int n4 = VOCAB*DMODEL/4;
        int tot = n0 + n1 + n2 + n3 + n4;
        cvt_all_k<<<(tot+255)/256, 256>>>(in_proj_w, winf, n0,
                                          out_proj_w, woutf, n1,
                                          x_proj_w,  wxpf,  n2,
                                          dt_w,      wdtf,  n3,
                                          embed,     wembf, n4);
    }

    embed_k<<<TTOK, 256>>>(tokens, embed, h);

    for (int L = 0; L < NLAYER; L++) {
        rmsnorm_k<<<TTOK, 256>>>(h, norm_w + (size_t)L * DMODEL, xnf);

        // in_proj: [2048,1024] x [4096,1024]^T -> xz
        mma_gemm<0,128,128,2><<<dim3(2*DINNER/128, TTOK/128), 256, SMEMB(128,128)>>>(
            xnf, DMODEL, winf + (size_t)L * 2*DINNER*DMODEL, DMODEL,
            xz, 2*DINNER, nullptr, 2*DINNER, DMODEL, 0);

        conv_silu_k<<<(TTOK*DINNER + 255)/256, 256>>>(
            xz, conv_w + (size_t)L * DINNER*DCONV, conv_b + (size_t)L * DINNER,
            xc, xcf);

        // x_proj split-K=8 at BM=128: grid (1,16,8)
        mma_gemm<0,128,128,2><<<dim3(1, TTOK/128, XP_SPLIT), 256, SMEMB(128,128)>>>(
            xcf, DINNER, wxpf + (size_t)L * XDBL_W*DINNER, DINNER,
            xpp, XDBL_W, nullptr, XDBL_W, DINNER/XP_SPLIT, TTOK*XDBL_W);

        reduce_xp_k<<<(TTOK*XDBL_W + 255)/256, 256>>>(xpp, xdbl, xdf);

        // dt: softplus(... + dt_b) at BM=128: grid (16,16)
        mma_gemm<2,128,128,2><<<dim3(DINNER/128, TTOK/128), 256, SMEMB(128,128)>>>(
            xdf, XDBL_W, wdtf + (size_t)L * DINNER*DTRANK, DTRANK,
            dts, DINNER, dt_b + (size_t)L * DINNER, DINNER, DTRANK, 0);

        scan_k<<<256, 256>>>(xdbl, dts, xc, xz,
                             A_log + (size_t)L * DINNER*DSTATE,
                             D_skip + (size_t)L * DINNER, yf);

        // out_proj split-K=2 at BM=128: grid (8,16,2) -> partials
        mma_gemm<0,128,128,2><<<dim3(DMODEL/128, TTOK/128, OP_SPLIT), 256, SMEMB(128,128)>>>(
            yf, DINNER, woutf + (size_t)L * DMODEL*DINNER, DINNER,
            opp, DMODEL, nullptr, DMODEL, DINNER/OP_SPLIT, TTOK*DMODEL);

        reduce_op_k<<<(TTOK*DMODEL/4 + 255)/256, 256>>>(opp, h);
    }

    rmsnorm_k<<<TTOK, 256>>>(h, final_norm_w, xnf);

    // logits: [2048,1024] x [32000,1024]^T
    mma_gemm<0,128,128,2><<<dim3(VOCAB/128, TTOK/128), 256, SMEMB(128,128)>>>(
        xnf, DMODEL, wembf, DMODEL, out, VOCAB, nullptr, VOCAB, DMODEL, 0);
}

// round 12
// speedup vs baseline: 3.1730x; 1.7301x over previous
#include <cuda_runtime.h>
#include <cuda_fp16.h>
#include <math.h>
#include <stdint.h>

#define BATCH   2
#define SEQ     1024
#define DMODEL  1024
#define NLAYER  4
#define VOCAB   32000
#define DSTATE  16
#define DCONV   4
#define DINNER  2048
#define DTRANK  64
#define TTOK    (BATCH*SEQ)
#define XDBL_W  96
#define XP_SPLIT 8
#define OP_SPLIT 2
#define SEG     8
#define SEGLEN  (SEQ/SEG)    // 128

// -------- fp32 scratch --------
__device__ float g_h   [TTOK*DMODEL];
__device__ float g_xz  [TTOK*2*DINNER];
__device__ float g_xc  [TTOK*DINNER];
__device__ float g_xdbl[TTOK*XDBL_W];
__device__ float g_dt  [TTOK*DINNER];
__device__ float g_xpp [XP_SPLIT*TTOK*XDBL_W];
__device__ float g_opp [OP_SPLIT*TTOK*DMODEL];
__device__ float g_Pseg[BATCH*DINNER*DSTATE*SEG];   // segment a-products
__device__ float g_Hseg[BATCH*DINNER*DSTATE*SEG];   // segment zero-state outputs
// -------- fp16 activations --------
__device__ __half g_xn_f[TTOK*DMODEL];
__device__ __half g_xc_f[TTOK*DINNER];
__device__ __half g_xd_f[TTOK*XDBL_W];
__device__ __half g_y_f [TTOK*DINNER];
// -------- fp16 weights --------
__device__ __half g_win_f [NLAYER*2*DINNER*DMODEL];
__device__ __half g_wout_f[NLAYER*DMODEL*DINNER];
__device__ __half g_wxp_f [NLAYER*XDBL_W*DINNER];
__device__ __half g_wdt_f [NLAYER*DINNER*DTRANK];
__device__ __half g_wemb_f[VOCAB*DMODEL];

// ---------------- helpers ----------------
__device__ __forceinline__ void cp16(uint32_t dst, const void* src, int srcBytes) {
    asm volatile("cp.async.cg.shared.global [%0], [%1], 16, %2;"
                 :: "r"(dst), "l"(src), "r"(srcBytes));
}
__device__ __forceinline__ void cp_commit() { asm volatile("cp.async.commit_group;"); }
template<int N> __device__ __forceinline__ void cp_wait() {
    asm volatile("cp.async.wait_group %0;" :: "n"(N));
}
__device__ __forceinline__ void ldsm4(uint32_t* r, uint32_t addr) {
    asm volatile("ldmatrix.sync.aligned.m8n8.x4.shared.b16 {%0,%1,%2,%3}, [%4];"
                 : "=r"(r[0]), "=r"(r[1]), "=r"(r[2]), "=r"(r[3]) : "r"(addr));
}
__device__ __forceinline__ void mma16(float* d, const uint32_t* a, uint32_t b0, uint32_t b1) {
    asm volatile(
        "mma.sync.aligned.m16n8k16.row.col.f32.f16.f16.f32 "
        "{%0,%1,%2,%3}, {%4,%5,%6,%7}, {%8,%9}, {%0,%1,%2,%3};\n"
        : "+f"(d[0]), "+f"(d[1]), "+f"(d[2]), "+f"(d[3])
        : "r"(a[0]), "r"(a[1]), "r"(a[2]), "r"(a[3]), "r"(b0), "r"(b1));
}
__device__ __forceinline__ uint32_t pack2h(float a, float b) {
    __half2 p = __floats2half2_rn(a, b);
    return *(uint32_t*)&p;
}

// ---------------- elementwise kernels ----------------
__global__ void cvt_all_k(const float* __restrict__ s0, __half* __restrict__ d0, int n0,
                          const float* __restrict__ s1, __half* __restrict__ d1, int n1,
                          const float* __restrict__ s2, __half* __restrict__ d2, int n2,
                          const float* __restrict__ s3, __half* __restrict__ d3, int n3,
                          const float* __restrict__ s4, __half* __restrict__ d4, int n4)
{
    int i = blockIdx.x * blockDim.x + threadIdx.x;
    const float* s; __half* d; int j = i;
    if (i < n0)                       { s = s0; d = d0; }
    else if ((j -= n0) < n1)          { s = s1; d = d1; }
    else if ((j -= n1) < n2)          { s = s2; d = d2; }
    else if ((j -= n2) < n3)          { s = s3; d = d3; }
    else if ((j -= n3) < n4)          { s = s4; d = d4; }
    else return;
    float4 v = ((const float4*)s)[j];
    uint2 p;
    p.x = pack2h(v.x, v.y);
    p.y = pack2h(v.z, v.w);
    ((uint2*)d)[j] = p;
}

__global__ void embed_k(const int* __restrict__ tok, const float* __restrict__ emb,
                        float* __restrict__ out)
{
    int t = blockIdx.x;
    int row = tok[t];
    ((float4*)(out + (size_t)t * DMODEL))[threadIdx.x] =
        ((const float4*)(emb + (size_t)row * DMODEL))[threadIdx.x];
}

__global__ void rmsnorm_k(const float* __restrict__ x, const float* __restrict__ w,
                          __half* __restrict__ oh)
{
    int t = blockIdx.x;
    int tid = threadIdx.x;
    float4 v = ((const float4*)(x + (size_t)t * DMODEL))[tid];
    float ss = v.x*v.x + v.y*v.y + v.z*v.z + v.w*v.w;
    __shared__ float sbuf[8];
    #pragma unroll
    for (int o = 16; o; o >>= 1) ss += __shfl_xor_sync(0xffffffffu, ss, o);
    int warp = tid >> 5, lane = tid & 31;
    if (lane == 0) sbuf[warp] = ss;
    __syncthreads();
    if (warp == 0) {
        float s2 = (lane < 8) ? sbuf[lane] : 0.f;
        #pragma unroll
        for (int o = 4; o; o >>= 1) s2 += __shfl_xor_sync(0xffffffffu, s2, o);
        if (lane == 0) sbuf[0] = rsqrtf(s2 * (1.0f / DMODEL) + 1e-5f);
    }
    __syncthreads();
    float r = sbuf[0];
    float4 wv = ((const float4*)w)[tid];
    uint2 p;
    p.x = pack2h(v.x*r*wv.x, v.y*r*wv.y);
    p.y = pack2h(v.z*r*wv.z, v.w*r*wv.w);
    ((uint2*)(oh + (size_t)t * DMODEL))[tid] = p;
}

__global__ void conv_silu_k(const float* __restrict__ xz, const float* __restrict__ cw,
                            const float* __restrict__ cb, float* __restrict__ xc,
                            __half* __restrict__ xch)
{
    int idx = blockIdx.x * blockDim.x + threadIdx.x;
    if (idx >= TTOK * DINNER) return;
    int c = idx % DINNER;
    int t = idx / DINNER;
    int l = t % SEQ;
    float4 w4 = *(const float4*)(cw + c * 4);
    const size_t str = 2 * DINNER;
    float acc = cb[c];
    if (l >= 3) acc += w4.x * xz[(size_t)(t-3)*str + c];
    if (l >= 2) acc += w4.y * xz[(size_t)(t-2)*str + c];
    if (l >= 1) acc += w4.z * xz[(size_t)(t-1)*str + c];
    acc += w4.w * xz[(size_t)t*str + c];
    float s = 1.f / (1.f + expf(-acc));
    float o = acc * s;
    xc[idx] = o;
    xch[idx] = __float2half_rn(o);
}

__global__ void reduce_xp_k(const float* __restrict__ parts,
                            float* __restrict__ xdbl, __half* __restrict__ xdf)
{
    int i = blockIdx.x * blockDim.x + threadIdx.x;
    if (i >= TTOK * XDBL_W) return;
    float s = 0.f;
    #pragma unroll
    for (int p = 0; p < XP_SPLIT; p++)
        s += parts[(size_t)p * TTOK * XDBL_W + i];
    xdbl[i] = s;
    xdf[i] = __float2half_rn(s);
}

__global__ void reduce_op_k(const float* __restrict__ parts, float* __restrict__ h)
{
    int i = blockIdx.x * blockDim.x + threadIdx.x;
    if (i >= TTOK * DMODEL / 4) return;
    float4 a = ((const float4*)parts)[i];
    float4 b = ((const float4*)(parts + (size_t)TTOK * DMODEL))[i];
    float4 o = ((float4*)h)[i];
    o.x += a.x + b.x; o.y += a.y + b.y;
    o.z += a.z + b.z; o.w += a.w + b.w;
    ((float4*)h)[i] = o;
}

// ---------------- segmented selective scan ----------------
// grid: 2048 blocks = B(2) x cgrp(128) x seg(8), 256 thr = 16 chan x 16 state
// Pass 1: per-segment (P = prod dA, H = h from zero state)
__global__ __launch_bounds__(256)
void scan1_k(const float* __restrict__ xdbl, const float* __restrict__ dt,
             const float* __restrict__ xc,   const float* __restrict__ A_log,
             float* __restrict__ Pseg, float* __restrict__ Hseg)
{
    int tid = threadIdx.x;
    int s = tid & 15;
    int bid = blockIdx.x;
    int seg  = bid & 7;
    int cgrp = (bid >> 3) & 127;
    int b    = bid >> 10;
    int c = (cgrp << 4) + (tid >> 4);

    float A = -expf(A_log[(size_t)c * DSTATE + s]);
    float P = 1.f, H = 0.f;
    int t0 = b * SEQ + seg * SEGLEN;
    #pragma unroll 4
    for (int l = 0; l < SEGLEN; l++) {
        int t = t0 + l;
        float dtv = dt[(size_t)t * DINNER + c];
        float xv  = xc[(size_t)t * DINNER + c];
        float Bv  = xdbl[(size_t)t * XDBL_W + DTRANK + s];
        float dA = __expf(dtv * A);
        H = dA * H + (dtv * xv) * Bv;
        P *= dA;
    }
    int idx = ((((b * DINNER + c) << 4) + s) << 3) + seg;
    Pseg[idx] = P;
    Hseg[idx] = H;
}

// Pass 2: fold predecessor segments (<=7 FMA) for h_in, replay segment, emit y
__global__ __launch_bounds__(256)
void scan2_k(const float* __restrict__ xdbl, const float* __restrict__ dt,
             const float* __restrict__ xc,   const float* __restrict__ xz,
             const float* __restrict__ A_log, const float* __restrict__ Dsk,
             const float* __restrict__ Pseg,  const float* __restrict__ Hseg,
             __half* __restrict__ yh)
{
    int tid = threadIdx.x;
    int s = tid & 15;
    int bid = blockIdx.x;
    int seg  = bid & 7;
    int cgrp = (bid >> 3) & 127;
    int b    = bid >> 10;
    int c = (cgrp << 4) + (tid >> 4);

    float A = -expf(A_log[(size_t)c * DSTATE + s]);
    float dval = Dsk[c];
    bool lane0 = (s == 0);

    int base = (((b * DINNER + c) << 4) + s) << 3;
    float h = 0.f;
    for (int j = 0; j < seg; j++)
        h = Pseg[base + j] * h + Hseg[base + j];

    int t0 = b * SEQ + seg * SEGLEN;
    #pragma unroll 4
    for (int l = 0; l < SEGLEN; l++) {
        int t = t0 + l;
        float dtv = dt[(size_t)t * DINNER + c];
        float xv  = xc[(size_t)t * DINNER + c];
        float Bv  = xdbl[(size_t)t * XDBL_W + DTRANK + s];
        float Cv  = xdbl[(size_t)t * XDBL_W + DTRANK + DSTATE + s];
        float dA = __expf(dtv * A);
        h = dA * h + (dtv * xv) * Bv;
        float p = h * Cv;
        p += __shfl_xor_sync(0xffffffffu, p, 8);
        p += __shfl_xor_sync(0xffffffffu, p, 4);
        p += __shfl_xor_sync(0xffffffffu, p, 2);
        p += __shfl_xor_sync(0xffffffffu, p, 1);
        if (lane0) {
            float z = xz[(size_t)t * (2*DINNER) + DINNER + c];
            float sg = 1.f / (1.f + __expf(-z));
            yh[(size_t)t * DINNER + c] = __float2half_rn((p + dval * xv) * (z * sg));
        }
    }
}

// ----------------------------------------------------------
// FP16 HMMA GEMM (NT) — unchanged from R11
// ----------------------------------------------------------
#define KCH     64
#define ROWB    144

template<int EPI, int BM, int BN, int MB>
__global__ __launch_bounds__(256, MB)
void mma_gemm(const __half* __restrict__ A, int lda,
              const __half* __restrict__ W, int ldw,
              float* __restrict__ C, int ldc,
              const float* __restrict__ bias,
              int N, int K, int zstride)
{
    constexpr int WM    = BM / 64;
    constexpr int WNW   = 8 / WM;
    constexpr int WN    = BN / WNW;
    constexpr int NFR   = WN / 8;
    constexpr int NBL   = WN / 16;
    constexpr int TILEA = BM * ROWB;
    constexpr int TILEB = BN * ROWB;
    constexpr int STAGE = TILEA + TILEB;
    constexpr int NTASK = (BM + BN) * 8;

    extern __shared__ char smem[];
    uint32_t sb = (uint32_t)__cvta_generic_to_shared(smem);

    int tid = threadIdx.x, lane = tid & 31, warp = tid >> 5;
    int wm = warp % WM;
    int wn = warp / WM;
    int tileM = blockIdx.y * BM, tileN = blockIdx.x * BN;

    int z = blockIdx.z;
    A += (size_t)z * K;
    W += (size_t)z * K;
    C += (size_t)z * zstride;

    float acc[4][NFR][4];
    #pragma unroll
    for (int mi = 0; mi < 4; mi++)
        #pragma unroll
        for (int ni = 0; ni < NFR; ni++)
            #pragma unroll
            for (int e = 0; e < 4; e++) acc[mi][ni][e] = 0.f;

    const int iters = K / KCH;

    uint32_t laneAoff = (uint32_t)((wm*64 + (lane & 15)) * ROWB + ((lane >> 4) & 1) * 16);
    uint32_t laneBoff = (uint32_t)((wn*WN + (lane & 7) + ((lane >= 16) ? 8 : 0)) * ROWB
                                   + ((lane >> 3) & 1) * 16);

    auto load_chunk = [&](int s, int it) {
        int k0 = it * KCH;
        uint32_t sbase = sb + (uint32_t)(s * STAGE);
        #pragma unroll
        for (int i = 0; i < NTASK/256; i++) {
            int task = tid + i * 256;
            if (task < BM*8) {
                int r = task >> 3, c = task & 7;
                cp16(sbase + (uint32_t)(r * ROWB + c * 16),
                     A + (size_t)(tileM + r) * lda + k0 + c * 8, 16);
            } else {
                int t2 = task - BM*8;
                int r = t2 >> 3, c = t2 & 7;
                int wr = tileN + r;
                const __half* src = W + (size_t)(wr < N ? wr : 0) * ldw + k0 + c * 8;
                cp16(sbase + (uint32_t)(TILEA + r * ROWB + c * 16),
                     src, wr < N ? 16 : 0);
            }
        }
        cp_commit();
    };

    if (iters > 0) load_chunk(0, 0);
    if (iters > 1) load_chunk(1, 1);

    for (int it = 0; it < iters; it++) {
        if (iters - 1 - it >= 1) cp_wait<1>();
        else                     cp_wait<0>();
        __syncthreads();
        if (it + 2 < iters) load_chunk((it + 2) % 3, it + 2);

        int s = it % 3;
        uint32_t stA = sb + s*STAGE + laneAoff;
        uint32_t stB = sb + s*STAGE + TILEA + laneBoff;

        #pragma unroll
        for (int ks = 0; ks < 4; ks++) {
            uint32_t a[4][4], b[NBL][4];
            #pragma unroll
            for (int mi = 0; mi < 4; mi++)
                ldsm4(a[mi], stA + mi*16*ROWB + ks*32);
            #pragma unroll
            for (int pi = 0; pi < NBL; pi++)
                ldsm4(b[pi], stB + pi*16*ROWB + ks*32);
            #pragma unroll
            for (int mi = 0; mi < 4; mi++)
                #pragma unroll
                for (int ni = 0; ni < NFR; ni++) {
                    int pi = ni >> 1, j = (ni & 1) * 2;
                    mma16(acc[mi][ni], a[mi], b[pi][j], b[pi][j+1]);
                }
        }
    }

    int g = lane >> 2, t4 = lane & 3;
    int warpN0 = tileN + wn*WN;
    #pragma unroll
    for (int mi = 0; mi < 4; mi++) {
        int r0 = tileM + wm*64 + mi*16 + g;
        #pragma unroll
        for (int ni = 0; ni < NFR; ni++) {
            int c = warpN0 + ni*8 + 2*t4;
            if (c >= N) continue;
            float2 v0 = make_float2(acc[mi][ni][0], acc[mi][ni][1]);
            float2 v1 = make_float2(acc[mi][ni][2], acc[mi][ni][3]);
            float* p0 = C + (size_t)r0 * ldc + c;
            float* p1 = C + (size_t)(r0 + 8) * ldc + c;
            if (EPI == 1) {
                float2 o0 = *(float2*)p0, o1 = *(float2*)p1;
                v0.x += o0.x; v0.y += o0.y; v1.x += o1.x; v1.y += o1.y;
            } else if (EPI == 2) {
                float b0 = bias[c], b1 = bias[c+1];
                v0.x += b0; v0.y += b1; v1.x += b0; v1.y += b1;
                v0.x = (v0.x > 20.f) ? v0.x : log1pf(expf(v0.x));
                v0.y = (v0.y > 20.f) ? v0.y : log1pf(expf(v0.y));
                v1.x = (v1.x > 20.f) ? v1.x : log1pf(expf(v1.x));
                v1.y = (v1.y > 20.f) ? v1.y : log1pf(expf(v1.y));
            }
            *(float2*)p0 = v0;
            *(float2*)p1 = v1;
        }
    }
}

#define SMEMB(BM,BN) (3 * ((BM) + (BN)) * ROWB)

// ----------------------------------------------------------
extern "C" void kernel_launch(void* const* d_in, const int* in_sizes, int n_in,
                              void* d_out, int out_size)
{
    const int*   tokens       = (const int*)  d_in[0];
    const float* embed        = (const float*)d_in[1];
    const float* norm_w       = (const float*)d_in[2];
    const float* in_proj_w    = (const float*)d_in[3];
    const float* conv_w       = (const float*)d_in[4];
    const float* conv_b       = (const float*)d_in[5];
    const float* x_proj_w     = (const float*)d_in[6];
    const float* dt_w         = (const float*)d_in[7];
    const float* dt_b         = (const float*)d_in[8];
    const float* A_log        = (const float*)d_in[9];
    const float* D_skip       = (const float*)d_in[10];
    const float* out_proj_w   = (const float*)d_in[11];
    const float* final_norm_w = (const float*)d_in[12];
    float* out = (float*)d_out;

    float *h, *xz, *xc, *xdbl, *dts, *xpp, *opp, *Ps, *Hs;
    __half *xnf,*xcf,*xdf,*yf;
    __half *winf,*woutf,*wxpf,*wdtf,*wembf;
    cudaGetSymbolAddress((void**)&h,    g_h);
    cudaGetSymbolAddress((void**)&xz,   g_xz);
    cudaGetSymbolAddress((void**)&xc,   g_xc);
    cudaGetSymbolAddress((void**)&xdbl, g_xdbl);
    cudaGetSymbolAddress((void**)&dts,  g_dt);
    cudaGetSymbolAddress((void**)&xpp,  g_xpp);
    cudaGetSymbolAddress((void**)&opp,  g_opp);
    cudaGetSymbolAddress((void**)&Ps,   g_Pseg);
    cudaGetSymbolAddress((void**)&Hs,   g_Hseg);
    cudaGetSymbolAddress((void**)&xnf,  g_xn_f);
    cudaGetSymbolAddress((void**)&xcf,  g_xc_f);
    cudaGetSymbolAddress((void**)&xdf,  g_xd_f);
    cudaGetSymbolAddress((void**)&yf,   g_y_f);
    cudaGetSymbolAddress((void**)&winf, g_win_f);
    cudaGetSymbolAddress((void**)&woutf,g_wout_f);
    cudaGetSymbolAddress((void**)&wxpf, g_wxp_f);
    cudaGetSymbolAddress((void**)&wdtf, g_wdt_f);
    cudaGetSymbolAddress((void**)&wembf,g_wemb_f);

    cudaFuncSetAttribute((const void*)mma_gemm<0,128,128,2>, cudaFuncAttributeMaxDynamicSharedMemorySize, SMEMB(128,128));
    cudaFuncSetAttribute((const void*)mma_gemm<2,128,128,2>, cudaFuncAttributeMaxDynamicSharedMemorySize, SMEMB(128,128));

    {
        int n0 = NLAYER*2*DINNER*DMODEL/4;
        int n1 = NLAYER*DMODEL*DINNER/4;
        int n2 = NLAYER*XDBL_W*DINNER/4;
        int n3 = NLAYER*DINNER*DTRANK/4;
        int n4 = VOCAB*DMODEL/4;
        int tot = n0 + n1 + n2 + n3 + n4;
        cvt_all_k<<<(tot+255)/256, 256>>>(in_proj_w, winf, n0,
                                          out_proj_w, woutf, n1,
                                          x_proj_w,  wxpf,  n2,
                                          dt_w,      wdtf,  n3,
                                          embed,     wembf, n4);
    }

    embed_k<<<TTOK, 256>>>(tokens, embed, h);

    for (int L = 0; L < NLAYER; L++) {
        rmsnorm_k<<<TTOK, 256>>>(h, norm_w + (size_t)L * DMODEL, xnf);

        mma_gemm<0,128,128,2><<<dim3(2*DINNER/128, TTOK/128), 256, SMEMB(128,128)>>>(
            xnf, DMODEL, winf + (size_t)L * 2*DINNER*DMODEL, DMODEL,
            xz, 2*DINNER, nullptr, 2*DINNER, DMODEL, 0);

        conv_silu_k<<<(TTOK*DINNER + 255)/256, 256>>>(
            xz, conv_w + (size_t)L * DINNER*DCONV, conv_b + (size_t)L * DINNER,
            xc, xcf);

        mma_gemm<0,128,128,2><<<dim3(1, TTOK/128, XP_SPLIT), 256, SMEMB(128,128)>>>(
            xcf, DINNER, wxpf + (size_t)L * XDBL_W*DINNER, DINNER,
            xpp, XDBL_W, nullptr, XDBL_W, DINNER/XP_SPLIT, TTOK*XDBL_W);

        reduce_xp_k<<<(TTOK*XDBL_W + 255)/256, 256>>>(xpp, xdbl, xdf);

        mma_gemm<2,128,128,2><<<dim3(DINNER/128, TTOK/128), 256, SMEMB(128,128)>>>(
            xdf, XDBL_W, wdtf + (size_t)L * DINNER*DTRANK, DTRANK,
            dts, DINNER, dt_b + (size_t)L * DINNER, DINNER, DTRANK, 0);

        // segmented scan: pass 1 (segment summaries), pass 2 (fold + emit)
        scan1_k<<<BATCH*128*SEG, 256>>>(xdbl, dts, xc,
                                        A_log + (size_t)L * DINNER*DSTATE, Ps, Hs);
        scan2_k<<<BATCH*128*SEG, 256>>>(xdbl, dts, xc, xz,
                                        A_log + (size_t)L * DINNER*DSTATE,
                                        D_skip + (size_t)L * DINNER, Ps, Hs, yf);

        mma_gemm<0,128,128,2><<<dim3(DMODEL/128, TTOK/128, OP_SPLIT), 256, SMEMB(128,128)>>>(
            yf, DINNER, woutf + (size_t)L * DMODEL*DINNER, DINNER,
            opp, DMODEL, nullptr, DMODEL, DINNER/OP_SPLIT, TTOK*DMODEL);

        reduce_op_k<<<(TTOK*DMODEL/4 + 255)/256, 256>>>(opp, h);
    }

    rmsnorm_k<<<TTOK, 256>>>(h, final_norm_w, xnf);

    mma_gemm<0,128,128,2><<<dim3(VOCAB/128, TTOK/128), 256, SMEMB(128,128)>>>(
        xnf, DMODEL, wembf, DMODEL, out, VOCAB, nullptr, VOCAB, DMODEL, 0);
}